// round 12
// baseline (speedup 1.0000x reference)
#include <cuda_runtime.h>
#include <math.h>
#include <stdint.h>

#define D_MODEL 768
#define D_INNER 1536
#define D_STATE 16
#define D_CONV  4
#define DT_RANK 48
#define BATCH   2
#define SEQ     2048
#define NTOK    (BATCH*SEQ)
#define XPROJ   80
#define SCCH    16                 // scan chunks
#define SCLEN   (SEQ/SCCH)         // 128 steps per chunk

#define BK      32
#define NST     3
#define PANEL_F 4096               // floats per 128x32 panel
#define STAGE_B 16384
#define DYN_SMEM (NST * STAGE_B * 2)   // 96KB -> 2 CTAs/SM

// ---------------- scratch (static device globals; no allocs) ----------------
static __device__ float g_xz   [2][NTOK][2*D_INNER];
static __device__ float g_xc   [2][NTOK][D_INNER];
static __device__ float g_xcr  [2][NTOK*D_INNER];       // A-shuffled
static __device__ float g_xdbl [2][NTOK][XPROJ];
static __device__ float g_xppart[8][NTOK][XPROJ];
static __device__ float g_dtr  [2][NTOK*64];            // A-shuffled
static __device__ float g_dt   [2][NTOK][D_INNER];
static __device__ float g_y    [2][NTOK*D_INNER];       // A-shuffled
static __device__ float g_opart[2][NTOK][D_MODEL];
static __device__ float g_hidr [NTOK*D_MODEL];
static __device__ float g_inWr [2][2*D_INNER*D_MODEL];
static __device__ float g_xpWr [2][128*D_INNER];
static __device__ float g_dtWr [2][D_INNER*64];
static __device__ float g_outWr[2][D_MODEL*D_INNER];
// chunked-scan state
static __device__ float g_S  [2][BATCH][SCCH][D_STATE][D_INNER];
static __device__ float g_sdt[2][BATCH][SCCH][D_INNER];
static __device__ float g_hin[2][BATCH][SCCH][D_STATE][D_INNER];

__device__ __forceinline__ float siluf(float v)     { return v / (1.f + __expf(-v)); }
__device__ __forceinline__ float softplusf(float v) { return fmaxf(v, 0.f) + log1pf(__expf(-fabsf(v))); }
__device__ __forceinline__ float rtf(float f) {
    uint32_t r; asm("cvt.rna.tf32.f32 %0, %1;" : "=r"(r) : "f"(f));
    return __uint_as_float(r);
}
__device__ __forceinline__ int a_shuf_idx(int row, int k, int panelsTot) {
    int mt = row >> 7, r = row & 127, p = k >> 5, kk = k & 31;
    return (mt * panelsTot + p) * PANEL_F
         + ((r >> 4) * 4 + (kk >> 3)) * 128
         + ((r & 7) * 4 + (kk & 3)) * 4 + ((r >> 3) & 1) + ((kk >> 2) & 1) * 2;
}
__device__ __forceinline__ int b_shuf_idx(int row, int k, int panelsTot) {
    int ng = row >> 7, n = row & 127, p = k >> 5, kk = k & 31;
    return (ng * panelsTot + p) * PANEL_F
         + ((n >> 3) * 4 + (kk >> 3)) * 64
         + ((n & 7) * 4 + (kk & 3)) * 2 + ((kk >> 2) & 1);
}
__device__ __forceinline__ uint32_t smem_u32(const void* p) {
    uint32_t a;
    asm("{ .reg .u64 t; cvta.to.shared.u64 t, %1; cvt.u32.u64 %0, t; }" : "=r"(a) : "l"(p));
    return a;
}
__device__ __forceinline__ void cpasync16(uint32_t dst, const void* src) {
    asm volatile("cp.async.cg.shared.global [%0], [%1], 16;"
                 :: "r"(dst), "l"(src) : "memory");
}
#define CP_COMMIT() asm volatile("cp.async.commit_group;" ::: "memory")
#define CP_WAIT1()  asm volatile("cp.async.wait_group 1;" ::: "memory")

__device__ __forceinline__ void mma8(float* d, const uint32_t* a, const uint32_t* b) {
    asm volatile(
        "mma.sync.aligned.m16n8k8.row.col.f32.tf32.tf32.f32 "
        "{%0,%1,%2,%3}, {%4,%5,%6,%7}, {%8,%9}, {%0,%1,%2,%3};"
        : "+f"(d[0]), "+f"(d[1]), "+f"(d[2]), "+f"(d[3])
        : "r"(a[0]), "r"(a[1]), "r"(a[2]), "r"(a[3]), "r"(b[0]), "r"(b[1]));
}

// load Av and check geometric structure A_n = n*A_1
__device__ __forceinline__ bool load_Av(const float* Alog, int d, float* Av) {
    bool fast = true;
#pragma unroll
    for (int n = 0; n < D_STATE; n++) {
        Av[n] = -__expf(Alog[d * D_STATE + n]);
        fast = fast && (fabsf(Av[n] - (n + 1) * Av[0]) <= 1e-3f * fabsf(Av[n]) + 1e-9f);
    }
    return fast;
}

// ---------------------------------------------------------------------------
// tf32 GEMM, fragment-shuffled operands, 64x64 warp tile (4 warps / CTA).
// LDS per chunk = 16KB*(2+2) = 64KB -> balanced with tensor pipe.
// ---------------------------------------------------------------------------
__global__ void __launch_bounds__(128, 2) gemm_tc(
    const float* A0, const float* A1,
    const float* B0, const float* B1,
    int panelsTot, int nchLoc, int zDiv,
    float* C, long long cZStride, int ldc, int Nfull,
    const float* bias0, const float* bias1, int mode)
{
    extern __shared__ float dsm[];
    const uint32_t aA = smem_u32(dsm);
    const uint32_t aB = aA + NST * STAGE_B;

    const int tid    = threadIdx.x;
    const int lane   = tid & 31;
    const int wid    = tid >> 5;
    const int warp_m = wid & 1;          // 0..1 -> 64 rows
    const int warp_n = wid >> 1;         // 0..1 -> 64 cols
    const int g      = lane >> 2;
    const int t      = lane & 3;
    const int z      = blockIdx.z;
    const int dir    = z / zDiv;
    const int split  = z - dir * zDiv;
    const int bm     = blockIdx.y * 128;
    const int bn     = blockIdx.x * 128;

    const float* A = (dir ? A1 : A0)
        + (size_t)((bm >> 7) * panelsTot + split * nchLoc) * PANEL_F;
    const float* B = (dir ? B1 : B0)
        + (size_t)((bn >> 7) * panelsTot + split * nchLoc) * PANEL_F;
    const float* bias = dir ? bias1 : bias0;
    float* Cz = C + (long long)z * cZStride;

    // producer: 8 float4 per matrix per thread per chunk (pure linear copy)
    const float* pA = A + tid * 4;
    const float* pB = B + tid * 4;
    const uint32_t soff = (uint32_t)tid * 16;
    uint32_t stWr = 0;
    auto issue = [&]() {
#pragma unroll
        for (int i = 0; i < 8; i++) {
            cpasync16(aA + stWr + soff + i * 2048, pA + i * 512);
            cpasync16(aB + stWr + soff + i * 2048, pB + i * 512);
        }
        CP_COMMIT();
        pA += PANEL_F; pB += PANEL_F;
        stWr += STAGE_B;
        if (stWr == NST * STAGE_B) stWr = 0;
    };

    float acc[4][8][4];
#pragma unroll
    for (int mi = 0; mi < 4; mi++)
#pragma unroll
        for (int ni = 0; ni < 8; ni++)
#pragma unroll
            for (int r = 0; r < 4; r++) acc[mi][ni][r] = 0.f;

    issue();
    issue();

    uint32_t stRd = 0;
    for (int c = 0; c < nchLoc; c++) {
        CP_WAIT1();
        __syncthreads();
        if (c + NST - 1 < nchLoc) issue();
        else                      CP_COMMIT();

        const float* A_ = dsm + (stRd >> 2);
        const float* B_ = A_ + NST * PANEL_F;
        stRd += STAGE_B;
        if (stRd == NST * STAGE_B) stRd = 0;

#pragma unroll
        for (int ks = 0; ks < 4; ks++) {
            float4 af[4];
            float2 bf[8];
#pragma unroll
            for (int mi = 0; mi < 4; mi++)
                af[mi] = *(const float4*)(A_ + ((warp_m * 4 + mi) * 4 + ks) * 128 + lane * 4);
#pragma unroll
            for (int ni = 0; ni < 8; ni++)
                bf[ni] = *(const float2*)(B_ + ((warp_n * 8 + ni) * 4 + ks) * 64 + lane * 2);
#pragma unroll
            for (int mi = 0; mi < 4; mi++) {
                uint32_t au[4] = { __float_as_uint(af[mi].x), __float_as_uint(af[mi].y),
                                   __float_as_uint(af[mi].z), __float_as_uint(af[mi].w) };
#pragma unroll
                for (int ni = 0; ni < 8; ni++) {
                    uint32_t bu[2] = { __float_as_uint(bf[ni].x), __float_as_uint(bf[ni].y) };
                    mma8(acc[mi][ni], au, bu);
                }
            }
        }
    }

#pragma unroll
    for (int mi = 0; mi < 4; mi++) {
        int row = bm + warp_m * 64 + mi * 16 + g;
#pragma unroll
        for (int ni = 0; ni < 8; ni++) {
            int col = bn + warp_n * 64 + ni * 8 + t * 2;
            if (col < Nfull) {
                float v00 = acc[mi][ni][0], v01 = acc[mi][ni][1];
                float v10 = acc[mi][ni][2], v11 = acc[mi][ni][3];
                if (mode == 2) {
                    float b0 = bias[col], b1 = bias[col + 1];
                    v00 = softplusf(v00 + b0); v01 = softplusf(v01 + b1);
                    v10 = softplusf(v10 + b0); v11 = softplusf(v11 + b1);
                }
                *(float2*)(Cz + (size_t)row * ldc + col)       = make_float2(v00, v01);
                *(float2*)(Cz + (size_t)(row + 8) * ldc + col) = make_float2(v10, v11);
            }
        }
    }
}

// ---------------------------------------------------------------------------
// Shuffle pre-passes (3 launches; in_proj gemm is launch #4 for ncu)
// ---------------------------------------------------------------------------
__global__ void shufA_k(float* __restrict__ dst, const float* __restrict__ src,
                        int rows, int K) {
    int i = blockIdx.x * blockDim.x + threadIdx.x;
    if (i < rows * K) {
        int row = i / K, k = i - row * K;
        dst[a_shuf_idx(row, k, K >> 5)] = rtf(src[i]);
    }
}
__global__ void shufB2_k(float* __restrict__ d0, const float* __restrict__ s0,
                         float* __restrict__ d1, const float* __restrict__ s1,
                         int rows, int rowsPad, int Kin, int Kpad) {
    int i = blockIdx.x * blockDim.x + threadIdx.x;
    if (i < rowsPad * Kpad) {
        int row = i / Kpad, k = i - row * Kpad;
        int idx = b_shuf_idx(row, k, Kpad >> 5);
        bool ok = (row < rows) && (k < Kin);
        d0[idx] = ok ? rtf(s0[row * Kin + k]) : 0.f;
        d1[idx] = ok ? rtf(s1[row * Kin + k]) : 0.f;
    }
}
#define N_XPW  (128 * D_INNER)
#define N_OUTW (D_MODEL * D_INNER)
#define N_DTW  (D_INNER * 64)
__global__ void shufW3_k(
    float* __restrict__ xd0, const float* __restrict__ xs0,
    float* __restrict__ xd1, const float* __restrict__ xs1,
    float* __restrict__ od0, const float* __restrict__ os0,
    float* __restrict__ od1, const float* __restrict__ os1,
    float* __restrict__ dd0, const float* __restrict__ ds0,
    float* __restrict__ dd1, const float* __restrict__ ds1)
{
    int i = blockIdx.x * blockDim.x + threadIdx.x;
    if (i < N_XPW) {
        int row = i / D_INNER, k = i - row * D_INNER;
        int idx = b_shuf_idx(row, k, D_INNER >> 5);
        bool ok = row < XPROJ;
        xd0[idx] = ok ? rtf(xs0[row * D_INNER + k]) : 0.f;
        xd1[idx] = ok ? rtf(xs1[row * D_INNER + k]) : 0.f;
    } else if (i < N_XPW + N_OUTW) {
        int j = i - N_XPW;
        int row = j / D_INNER, k = j - row * D_INNER;
        int idx = b_shuf_idx(row, k, D_INNER >> 5);
        od0[idx] = rtf(os0[row * D_INNER + k]);
        od1[idx] = rtf(os1[row * D_INNER + k]);
    } else if (i < N_XPW + N_OUTW + N_DTW) {
        int j = i - N_XPW - N_OUTW;
        int row = j >> 6, k = j & 63;
        int idx = b_shuf_idx(row, k, 2);
        bool ok = k < DT_RANK;
        dd0[idx] = ok ? rtf(ds0[row * DT_RANK + k]) : 0.f;
        dd1[idx] = ok ? rtf(ds1[row * DT_RANK + k]) : 0.f;
    }
}

__global__ void xp_reduce_kernel() {
    int i = blockIdx.x * blockDim.x + threadIdx.x;
    if (i >= 2 * NTOK * XPROJ) return;
    int c   = i % XPROJ;
    int tk  = (i / XPROJ) % NTOK;
    int dir = i / (XPROJ * NTOK);
    float s = g_xppart[dir * 4 + 0][tk][c] + g_xppart[dir * 4 + 1][tk][c]
            + g_xppart[dir * 4 + 2][tk][c] + g_xppart[dir * 4 + 3][tk][c];
    g_xdbl[dir][tk][c] = s;
    if (c < DT_RANK)  g_dtr[dir][a_shuf_idx(tk, c, 2)] = rtf(s);
    else if (c < 64)  g_dtr[dir][a_shuf_idx(tk, c, 2)] = 0.f;
}

__global__ void out_add_kernel(float* __restrict__ out) {
    int i = blockIdx.x * blockDim.x + threadIdx.x;
    if (i < NTOK * D_MODEL / 4) {
        float4 a = ((const float4*)&g_opart[0][0][0])[i];
        float4 b = ((const float4*)&g_opart[1][0][0])[i];
        a.x += b.x; a.y += b.y; a.z += b.z; a.w += b.w;
        ((float4*)out)[i] = a;
    }
}

// ---------------------------------------------------------------------------
// Depthwise causal conv + bias + SiLU: 8 timesteps/thread, rolling window.
// ---------------------------------------------------------------------------
__global__ void __launch_bounds__(256) conv_silu_kernel(
    const float* __restrict__ w_f, const float* __restrict__ b_f,
    const float* __restrict__ w_r, const float* __restrict__ b_r)
{
    int d  = blockIdx.x * 256 + threadIdx.x;
    int t0 = blockIdx.y * 8;
    int zb = blockIdx.z;
    int dir = zb >> 1, b = zb & 1;

    const float* wsrc = dir ? w_r : w_f;
    float w0 = wsrc[d * D_CONV + 0], w1 = wsrc[d * D_CONV + 1];
    float w2 = wsrc[d * D_CONV + 2], w3 = wsrc[d * D_CONV + 3];
    float bias = (dir ? b_r : b_f)[d];

    int base = dir ? t0 : t0 - 3;
    float xv[11];
#pragma unroll
    for (int j = 0; j < 11; j++) {
        int tt = base + j;
        xv[j] = (tt >= 0 && tt < SEQ) ? g_xz[dir][b * SEQ + tt][d] : 0.f;
    }
#pragma unroll
    for (int i = 0; i < 8; i++) {
        float acc;
        if (dir == 0)
            acc = bias + w0 * xv[i] + w1 * xv[i + 1] + w2 * xv[i + 2] + w3 * xv[i + 3];
        else
            acc = bias + w0 * xv[i + 3] + w1 * xv[i + 2] + w2 * xv[i + 1] + w3 * xv[i];
        float v = siluf(acc);
        int tok = b * SEQ + t0 + i;
        g_xc[dir][tok][d] = v;
        g_xcr[dir][a_shuf_idx(tok, d, D_INNER / 32)] = rtf(v);
    }
}

// ---------------------------------------------------------------------------
// Chunked selective scan (3 kernels).
// ---------------------------------------------------------------------------
__global__ void __launch_bounds__(128) scan_pass1(
    const float* __restrict__ Alog_f, const float* __restrict__ Alog_r)
{
    int dir = blockIdx.z / SCCH;
    int ci  = blockIdx.z % SCCH;
    int b   = blockIdx.y;
    int d   = blockIdx.x * 128 + threadIdx.x;

    float Av[D_STATE];
    bool fast = load_Av(dir ? Alog_r : Alog_f, d, Av);

    __shared__ float sB[SCLEN][D_STATE];
    for (int j = threadIdx.x; j < SCLEN * D_STATE; j += 128) {
        int lt = j >> 4, n = j & 15;
        int gs = ci * SCLEN + lt;
        int t  = dir ? (SEQ - 1 - gs) : gs;
        sB[lt][n] = g_xdbl[dir][b * SEQ + t][DT_RANK + n];
    }
    __syncthreads();

    float h[D_STATE];
#pragma unroll
    for (int n = 0; n < D_STATE; n++) h[n] = 0.f;
    float sdt = 0.f;

    for (int s = 0; s < SCLEN; s++) {
        int gs  = ci * SCLEN + s;
        int t   = dir ? (SEQ - 1 - gs) : gs;
        int tok = b * SEQ + t;
        float dt  = g_dt[dir][tok][d];
        float x   = g_xc[dir][tok][d];
        float dtx = dt * x;
        sdt += dt;
        if (fast) {
            float r = __expf(dt * Av[0]);
            float dA = r;
#pragma unroll
            for (int n = 0; n < D_STATE; n++) {
                h[n] = fmaf(dA, h[n], dtx * sB[s][n]);
                dA *= r;
            }
        } else {
#pragma unroll
            for (int n = 0; n < D_STATE; n++)
                h[n] = fmaf(__expf(dt * Av[n]), h[n], dtx * sB[s][n]);
        }
    }

    g_sdt[dir][b][ci][d] = sdt;
#pragma unroll
    for (int n = 0; n < D_STATE; n++) g_S[dir][b][ci][n][d] = h[n];
}

__global__ void __launch_bounds__(256) scan_prop(
    const float* __restrict__ Alog_f, const float* __restrict__ Alog_r)
{
    int i = blockIdx.x * 256 + threadIdx.x;
    if (i >= 2 * BATCH * D_INNER) return;
    int d   = i % D_INNER;
    int b   = (i / D_INNER) % BATCH;
    int dir = i / (D_INNER * BATCH);

    float Av[D_STATE];
    bool fast = load_Av(dir ? Alog_r : Alog_f, d, Av);

    float h[D_STATE];
#pragma unroll
    for (int n = 0; n < D_STATE; n++) h[n] = 0.f;

    for (int c = 0; c < SCCH; c++) {
#pragma unroll
        for (int n = 0; n < D_STATE; n++) g_hin[dir][b][c][n][d] = h[n];
        float sdt = g_sdt[dir][b][c][d];
        if (fast) {
            float r = __expf(sdt * Av[0]);
            float P = r;
#pragma unroll
            for (int n = 0; n < D_STATE; n++) {
                h[n] = fmaf(P, h[n], g_S[dir][b][c][n][d]);
                P *= r;
            }
        } else {
#pragma unroll
            for (int n = 0; n < D_STATE; n++)
                h[n] = fmaf(__expf(sdt * Av[n]), h[n], g_S[dir][b][c][n][d]);
        }
    }
}

__global__ void __launch_bounds__(128) scan_pass2(
    const float* __restrict__ Alog_f, const float* __restrict__ D_f,
    const float* __restrict__ Alog_r, const float* __restrict__ D_r)
{
    int dir = blockIdx.z / SCCH;
    int ci  = blockIdx.z % SCCH;
    int b   = blockIdx.y;
    int d   = blockIdx.x * 128 + threadIdx.x;

    float Av[D_STATE];
    bool fast = load_Av(dir ? Alog_r : Alog_f, d, Av);
    float Dv = (dir ? D_r : D_f)[d];

    __shared__ float sB[SCLEN][D_STATE];
    __shared__ float sC[SCLEN][D_STATE];
    for (int j = threadIdx.x; j < SCLEN * 2 * D_STATE; j += 128) {
        int lt = j >> 5, cc = j & 31;
        int gs = ci * SCLEN + lt;
        int t  = dir ? (SEQ - 1 - gs) : gs;
        float v = g_xdbl[dir][b * SEQ + t][DT_RANK + cc];
        if (cc < D_STATE) sB[lt][cc] = v;
        else              sC[lt][cc - D_STATE] = v;
    }
    __syncthreads();

    float h[D_STATE];
#pragma unroll
    for (int n = 0; n < D_STATE; n++) h[n] = g_hin[dir][b][ci][n][d];

    for (int s = 0; s < SCLEN; s++) {
        int gs  = ci * SCLEN + s;
        int t   = dir ? (SEQ - 1 - gs) : gs;
        int tok = b * SEQ + t;
        float dt  = g_dt[dir][tok][d];
        float x   = g_xc[dir][tok][d];
        float dtx = dt * x;
        float y = 0.f;
        if (fast) {
            float r = __expf(dt * Av[0]);
            float dA = r;
#pragma unroll
            for (int n = 0; n < D_STATE; n++) {
                h[n] = fmaf(dA, h[n], dtx * sB[s][n]);
                y    = fmaf(h[n], sC[s][n], y);
                dA *= r;
            }
        } else {
#pragma unroll
            for (int n = 0; n < D_STATE; n++) {
                h[n] = fmaf(__expf(dt * Av[n]), h[n], dtx * sB[s][n]);
                y    = fmaf(h[n], sC[s][n], y);
            }
        }
        float z = g_xz[dir][tok][D_INNER + d];
        g_y[dir][a_shuf_idx(tok, d, D_INNER / 32)] = rtf((y + x * Dv) * siluf(z));
    }
}

// ---------------------------------------------------------------------------
extern "C" void kernel_launch(void* const* d_in, const int* in_sizes, int n_in,
                              void* d_out, int out_size)
{
    (void)in_sizes; (void)n_in; (void)out_size;

    const float* hidden   = (const float*)d_in[0];
    const float* inW[2]   = {(const float*)d_in[1],  (const float*)d_in[10]};
    const float* convW[2] = {(const float*)d_in[2],  (const float*)d_in[11]};
    const float* convB[2] = {(const float*)d_in[3],  (const float*)d_in[12]};
    const float* xpW[2]   = {(const float*)d_in[4],  (const float*)d_in[13]};
    const float* dtW[2]   = {(const float*)d_in[5],  (const float*)d_in[14]};
    const float* dtB[2]   = {(const float*)d_in[6],  (const float*)d_in[15]};
    const float* Alog[2]  = {(const float*)d_in[7],  (const float*)d_in[16]};
    const float* Dp[2]    = {(const float*)d_in[8],  (const float*)d_in[17]};
    const float* outW[2]  = {(const float*)d_in[9],  (const float*)d_in[18]};
    float* out = (float*)d_out;

    float *xz, *xcr, *dtr, *dt, *y, *hidr, *inWr, *xpWr, *dtWr, *outWr, *xpp, *opart;
    cudaGetSymbolAddress((void**)&xz,    g_xz);
    cudaGetSymbolAddress((void**)&xcr,   g_xcr);
    cudaGetSymbolAddress((void**)&dtr,   g_dtr);
    cudaGetSymbolAddress((void**)&dt,    g_dt);
    cudaGetSymbolAddress((void**)&y,     g_y);
    cudaGetSymbolAddress((void**)&hidr,  g_hidr);
    cudaGetSymbolAddress((void**)&inWr,  g_inWr);
    cudaGetSymbolAddress((void**)&xpWr,  g_xpWr);
    cudaGetSymbolAddress((void**)&dtWr,  g_dtWr);
    cudaGetSymbolAddress((void**)&outWr, g_outWr);
    cudaGetSymbolAddress((void**)&xpp,   g_xppart);
    cudaGetSymbolAddress((void**)&opart, g_opart);

    cudaFuncSetAttribute(gemm_tc, cudaFuncAttributeMaxDynamicSharedMemorySize, DYN_SMEM);

    const long long szXC   = (long long)NTOK * D_INNER;
    const long long szXZ   = (long long)NTOK * 2 * D_INNER;
    const long long szINW  = (long long)2 * D_INNER * D_MODEL;
    const long long szXPW  = (long long)128 * D_INNER;
    const long long szDTW  = (long long)D_INNER * 64;
    const long long szOUTW = (long long)D_MODEL * D_INNER;
    const long long szDTR  = (long long)NTOK * 64;
    const long long szXPP  = (long long)NTOK * XPROJ;
    const long long szOP   = (long long)NTOK * D_MODEL;

    // 0) shuffle+round pre-passes — 3 launches
    {
        int n = NTOK * D_MODEL;
        shufA_k<<<(n + 255) / 256, 256>>>(hidr, hidden, NTOK, D_MODEL);
        n = 2 * D_INNER * D_MODEL;
        shufB2_k<<<(n + 255) / 256, 256>>>(inWr, inW[0], inWr + szINW, inW[1],
                                           2 * D_INNER, 2 * D_INNER, D_MODEL, D_MODEL);
        n = N_XPW + N_OUTW + N_DTW;
        shufW3_k<<<(n + 255) / 256, 256>>>(
            xpWr, xpW[0], xpWr + szXPW, xpW[1],
            outWr, outW[0], outWr + szOUTW, outW[1],
            dtWr, dtW[0], dtWr + szDTW, dtW[1]);
    }

    // 1) in_proj (launch #4 — ncu target)
    gemm_tc<<<dim3((2 * D_INNER) / 128, NTOK / 128, 2), 128, DYN_SMEM>>>(
        hidr, hidr, inWr, inWr + szINW,
        D_MODEL / 32, D_MODEL / 32, 1,
        xz, szXZ, 2 * D_INNER, 2 * D_INNER, nullptr, nullptr, 0);

    // 2) conv + silu
    conv_silu_kernel<<<dim3(D_INNER / 256, SEQ / 8, 4), 256>>>(
        convW[0], convB[0], convW[1], convB[1]);

    // 3) x_proj split-K x4 + reduce
    gemm_tc<<<dim3(1, NTOK / 128, 8), 128, DYN_SMEM>>>(
        xcr, xcr + szXC, xpWr, xpWr + szXPW,
        D_INNER / 32, D_INNER / 128, 4,
        xpp, szXPP, XPROJ, XPROJ, nullptr, nullptr, 0);
    xp_reduce_kernel<<<(2 * NTOK * XPROJ + 255) / 256, 256>>>();

    // 4) dt_proj + bias + softplus
    gemm_tc<<<dim3(D_INNER / 128, NTOK / 128, 2), 128, DYN_SMEM>>>(
        dtr, dtr + szDTR, dtWr, dtWr + szDTW,
        2, 2, 1,
        dt, szXC, D_INNER, D_INNER, dtB[0], dtB[1], 2);

    // 5) chunked selective scan
    scan_pass1<<<dim3(D_INNER / 128, BATCH, 2 * SCCH), 128>>>(Alog[0], Alog[1]);
    scan_prop<<<(2 * BATCH * D_INNER + 255) / 256, 256>>>(Alog[0], Alog[1]);
    scan_pass2<<<dim3(D_INNER / 128, BATCH, 2 * SCCH), 128>>>(
        Alog[0], Dp[0], Alog[1], Dp[1]);

    // 6) out_proj per-dir partials + add
    gemm_tc<<<dim3(D_MODEL / 128, NTOK / 128, 2), 128, DYN_SMEM>>>(
        y, y + szXC, outWr, outWr + szOUTW,
        D_INNER / 32, D_INNER / 32, 1,
        opart, szOP, D_MODEL, D_MODEL, nullptr, nullptr, 0);
    out_add_kernel<<<(NTOK * D_MODEL / 4 + 255) / 256, 256>>>(out);
}

// round 14
// speedup vs baseline: 1.2947x; 1.2947x over previous
#include <cuda_runtime.h>
#include <cuda_fp16.h>
#include <math.h>
#include <stdint.h>

#define D_MODEL 768
#define D_INNER 1536
#define D_STATE 16
#define D_CONV  4
#define DT_RANK 48
#define BATCH   2
#define SEQ     2048
#define NTOK    (BATCH*SEQ)
#define XPROJ   80
#define SCCH    16
#define SCLEN   (SEQ/SCCH)

#define BK      64
#define NST     3
#define PANEL_H 8192                   // halves per 128x64 panel (16KB)
#define STAGE_B 16384                  // bytes per stage per matrix
#define DYN_SMEM (NST * STAGE_B * 2)   // 96KB -> 2 CTAs/SM

// ---------------- scratch (static device globals; no allocs) ----------------
static __device__ float  g_xz   [2][NTOK][2*D_INNER];
static __device__ float  g_xc   [2][NTOK][D_INNER];
static __device__ __half g_xcr  [2][NTOK*D_INNER];      // A-shuffled fp16
static __device__ float  g_xdbl [2][NTOK][XPROJ];
static __device__ float  g_xppart[8][NTOK][XPROJ];
static __device__ __half g_dtr  [2][NTOK*128];          // A-shuffled, K pad 128
static __device__ float  g_dt   [2][NTOK][D_INNER];
static __device__ __half g_y    [2][NTOK*D_INNER];      // A-shuffled fp16
static __device__ float  g_opart[2][NTOK][D_MODEL];
static __device__ __half g_hidr [NTOK*D_MODEL];
static __device__ __half g_inWr [2][2*D_INNER*D_MODEL];
static __device__ __half g_xpWr [2][128*D_INNER];
static __device__ __half g_dtWr [2][D_INNER*128];
static __device__ __half g_outWr[2][D_MODEL*D_INNER];
// chunked-scan state
static __device__ float g_S  [2][BATCH][SCCH][D_STATE][D_INNER];
static __device__ float g_sdt[2][BATCH][SCCH][D_INNER];
static __device__ float g_hin[2][BATCH][SCCH][D_STATE][D_INNER];

__device__ __forceinline__ float siluf(float v)     { return v / (1.f + __expf(-v)); }
__device__ __forceinline__ float softplusf(float v) { return fmaxf(v, 0.f) + log1pf(__expf(-fabsf(v))); }

// fragment-packed fp16 layouts for mma.m16n8k16 (indices in half units)
// A tile: 16 rows x 16 k = 256 halves; lane holds 4 regs (uint4).
__device__ __forceinline__ int a_shuf_idx_h(int row, int k, int panelsTot) {
    int grp = row >> 7, r7 = row & 127, mt = r7 >> 4, r = r7 & 15;
    int p = k >> 6, k6 = k & 63, kt = k6 >> 4, kk = k6 & 15;
    int lane = (r & 7) * 4 + ((kk >> 1) & 3);
    int reg  = ((r >> 3) & 1) + ((kk >> 3) << 1);
    return (grp * panelsTot + p) * PANEL_H + (mt * 4 + kt) * 256 + lane * 8 + reg * 2 + (kk & 1);
}
// B tile: 8 n x 16 k = 128 halves; lane holds 2 regs (uint2).
__device__ __forceinline__ int b_shuf_idx_h(int n, int k, int panelsTot) {
    int grp = n >> 7, n7 = n & 127, nt = n7 >> 3, nn = n7 & 7;
    int p = k >> 6, k6 = k & 63, kt = k6 >> 4, kk = k6 & 15;
    int lane = nn * 4 + ((kk >> 1) & 3);
    int reg  = kk >> 3;
    return (grp * panelsTot + p) * PANEL_H + (nt * 4 + kt) * 128 + lane * 4 + reg * 2 + (kk & 1);
}
__device__ __forceinline__ uint32_t smem_u32(const void* p) {
    uint32_t a;
    asm("{ .reg .u64 t; cvta.to.shared.u64 t, %1; cvt.u32.u64 %0, t; }" : "=r"(a) : "l"(p));
    return a;
}
__device__ __forceinline__ void cpasync16(uint32_t dst, const void* src) {
    asm volatile("cp.async.cg.shared.global [%0], [%1], 16;"
                 :: "r"(dst), "l"(src) : "memory");
}
#define CP_COMMIT() asm volatile("cp.async.commit_group;" ::: "memory")
#define CP_WAIT1()  asm volatile("cp.async.wait_group 1;" ::: "memory")

__device__ __forceinline__ void mma16h(float* d, const uint32_t* a, const uint32_t* b) {
    asm volatile(
        "mma.sync.aligned.m16n8k16.row.col.f32.f16.f16.f32 "
        "{%0,%1,%2,%3}, {%4,%5,%6,%7}, {%8,%9}, {%0,%1,%2,%3};"
        : "+f"(d[0]), "+f"(d[1]), "+f"(d[2]), "+f"(d[3])
        : "r"(a[0]), "r"(a[1]), "r"(a[2]), "r"(a[3]), "r"(b[0]), "r"(b[1]));
}

// load Av and check geometric structure A_n = n*A_1
__device__ __forceinline__ bool load_Av(const float* Alog, int d, float* Av) {
    bool fast = true;
#pragma unroll
    for (int n = 0; n < D_STATE; n++) {
        Av[n] = -__expf(Alog[d * D_STATE + n]);
        fast = fast && (fabsf(Av[n] - (n + 1) * Av[0]) <= 1e-3f * fabsf(Av[n]) + 1e-9f);
    }
    return fast;
}

// ---------------------------------------------------------------------------
// fp16 GEMM (m16n8k16), fragment-shuffled operands. 128x128 CTA tile, BK=64,
// 64x64 warp tile (4 warps), 3-stage cp.async, linear panel copies.
// z: dir = z/zDiv, split = z%zDiv. mode 0: store; 2: softplus(v + bias[n]).
// ---------------------------------------------------------------------------
__global__ void __launch_bounds__(128, 2) gemm_tc(
    const __half* A0, const __half* A1,
    const __half* B0, const __half* B1,
    int panelsTot, int nchLoc, int zDiv,
    float* C, long long cZStride, int ldc, int Nfull,
    const float* bias0, const float* bias1, int mode)
{
    extern __shared__ __half hsm[];
    const uint32_t aA = smem_u32(hsm);
    const uint32_t aB = aA + NST * STAGE_B;

    const int tid    = threadIdx.x;
    const int lane   = tid & 31;
    const int wid    = tid >> 5;
    const int warp_m = wid & 1;
    const int warp_n = wid >> 1;
    const int g      = lane >> 2;
    const int t      = lane & 3;
    const int z      = blockIdx.z;
    const int dir    = z / zDiv;
    const int split  = z - dir * zDiv;
    const int bm     = blockIdx.y * 128;
    const int bn     = blockIdx.x * 128;

    const __half* A = (dir ? A1 : A0)
        + (size_t)((bm >> 7) * panelsTot + split * nchLoc) * PANEL_H;
    const __half* B = (dir ? B1 : B0)
        + (size_t)((bn >> 7) * panelsTot + split * nchLoc) * PANEL_H;
    const float* bias = dir ? bias1 : bias0;
    float* Cz = C + (long long)z * cZStride;

    // producer: 8x16B per matrix per thread per chunk (pure linear copy)
    const __half* pA = A + tid * 8;
    const __half* pB = B + tid * 8;
    const uint32_t soff = (uint32_t)tid * 16;
    uint32_t stWr = 0;
    auto issue = [&]() {
#pragma unroll
        for (int i = 0; i < 8; i++) {
            cpasync16(aA + stWr + soff + i * 2048, pA + i * 1024);
            cpasync16(aB + stWr + soff + i * 2048, pB + i * 1024);
        }
        CP_COMMIT();
        pA += PANEL_H; pB += PANEL_H;
        stWr += STAGE_B;
        if (stWr == NST * STAGE_B) stWr = 0;
    };

    float acc[4][8][4];
#pragma unroll
    for (int mi = 0; mi < 4; mi++)
#pragma unroll
        for (int ni = 0; ni < 8; ni++)
#pragma unroll
            for (int r = 0; r < 4; r++) acc[mi][ni][r] = 0.f;

    issue();
    issue();

    uint32_t stRd = 0;
    for (int c = 0; c < nchLoc; c++) {
        CP_WAIT1();
        __syncthreads();
        if (c + NST - 1 < nchLoc) issue();
        else                      CP_COMMIT();

        const __half* A_ = hsm + (stRd >> 1);
        const __half* B_ = A_ + NST * PANEL_H;
        stRd += STAGE_B;
        if (stRd == NST * STAGE_B) stRd = 0;

#pragma unroll
        for (int ks = 0; ks < 4; ks++) {
            uint4 af[4];
            uint2 bf[8];
#pragma unroll
            for (int mi = 0; mi < 4; mi++)
                af[mi] = *(const uint4*)(A_ + ((warp_m * 4 + mi) * 4 + ks) * 256 + lane * 8);
#pragma unroll
            for (int ni = 0; ni < 8; ni++)
                bf[ni] = *(const uint2*)(B_ + ((warp_n * 8 + ni) * 4 + ks) * 128 + lane * 4);
#pragma unroll
            for (int mi = 0; mi < 4; mi++) {
                uint32_t au[4] = { af[mi].x, af[mi].y, af[mi].z, af[mi].w };
#pragma unroll
                for (int ni = 0; ni < 8; ni++) {
                    uint32_t bu[2] = { bf[ni].x, bf[ni].y };
                    mma16h(acc[mi][ni], au, bu);
                }
            }
        }
    }

#pragma unroll
    for (int mi = 0; mi < 4; mi++) {
        int row = bm + warp_m * 64 + mi * 16 + g;
#pragma unroll
        for (int ni = 0; ni < 8; ni++) {
            int col = bn + warp_n * 64 + ni * 8 + t * 2;
            if (col < Nfull) {
                float v00 = acc[mi][ni][0], v01 = acc[mi][ni][1];
                float v10 = acc[mi][ni][2], v11 = acc[mi][ni][3];
                if (mode == 2) {
                    float b0 = bias[col], b1 = bias[col + 1];
                    v00 = softplusf(v00 + b0); v01 = softplusf(v01 + b1);
                    v10 = softplusf(v10 + b0); v11 = softplusf(v11 + b1);
                }
                *(float2*)(Cz + (size_t)row * ldc + col)       = make_float2(v00, v01);
                *(float2*)(Cz + (size_t)(row + 8) * ldc + col) = make_float2(v10, v11);
            }
        }
    }
}

// ---------------------------------------------------------------------------
// Shuffle pre-passes (3 launches; in_proj gemm is launch #4 for ncu)
// ---------------------------------------------------------------------------
__global__ void shufA_k(__half* __restrict__ dst, const float* __restrict__ src,
                        int rows, int K) {
    int i = blockIdx.x * blockDim.x + threadIdx.x;
    if (i < rows * K) {
        int row = i / K, k = i - row * K;
        dst[a_shuf_idx_h(row, k, K >> 6)] = __float2half(src[i]);
    }
}
__global__ void shufB2_k(__half* __restrict__ d0, const float* __restrict__ s0,
                         __half* __restrict__ d1, const float* __restrict__ s1,
                         int rows, int rowsPad, int Kin, int Kpad) {
    int i = blockIdx.x * blockDim.x + threadIdx.x;
    if (i < rowsPad * Kpad) {
        int row = i / Kpad, k = i - row * Kpad;
        int idx = b_shuf_idx_h(row, k, Kpad >> 6);
        bool ok = (row < rows) && (k < Kin);
        d0[idx] = __float2half(ok ? s0[row * Kin + k] : 0.f);
        d1[idx] = __float2half(ok ? s1[row * Kin + k] : 0.f);
    }
}
#define N_XPW  (128 * D_INNER)
#define N_OUTW (D_MODEL * D_INNER)
#define N_DTW  (D_INNER * 128)
__global__ void shufW3_k(
    __half* __restrict__ xd0, const float* __restrict__ xs0,
    __half* __restrict__ xd1, const float* __restrict__ xs1,
    __half* __restrict__ od0, const float* __restrict__ os0,
    __half* __restrict__ od1, const float* __restrict__ os1,
    __half* __restrict__ dd0, const float* __restrict__ ds0,
    __half* __restrict__ dd1, const float* __restrict__ ds1)
{
    int i = blockIdx.x * blockDim.x + threadIdx.x;
    if (i < N_XPW) {
        int row = i / D_INNER, k = i - row * D_INNER;
        int idx = b_shuf_idx_h(row, k, D_INNER >> 6);
        bool ok = row < XPROJ;
        xd0[idx] = __float2half(ok ? xs0[row * D_INNER + k] : 0.f);
        xd1[idx] = __float2half(ok ? xs1[row * D_INNER + k] : 0.f);
    } else if (i < N_XPW + N_OUTW) {
        int j = i - N_XPW;
        int row = j / D_INNER, k = j - row * D_INNER;
        int idx = b_shuf_idx_h(row, k, D_INNER >> 6);
        od0[idx] = __float2half(os0[row * D_INNER + k]);
        od1[idx] = __float2half(os1[row * D_INNER + k]);
    } else if (i < N_XPW + N_OUTW + N_DTW) {
        int j = i - N_XPW - N_OUTW;
        int row = j >> 7, k = j & 127;
        int idx = b_shuf_idx_h(row, k, 2);
        bool ok = k < DT_RANK;
        dd0[idx] = __float2half(ok ? ds0[row * DT_RANK + k] : 0.f);
        dd1[idx] = __float2half(ok ? ds1[row * DT_RANK + k] : 0.f);
    }
}

// x_proj split-K reduce: xdbl exact + dtr (A-shuffled fp16, K pad 128)
__global__ void xp_reduce_kernel() {
    int i = blockIdx.x * blockDim.x + threadIdx.x;   // 2*NTOK*128
    if (i >= 2 * NTOK * 128) return;
    int c   = i & 127;
    int tk  = (i >> 7) % NTOK;
    int dir = i / (128 * NTOK);
    float s = 0.f;
    if (c < XPROJ) {
        s = g_xppart[dir * 4 + 0][tk][c] + g_xppart[dir * 4 + 1][tk][c]
          + g_xppart[dir * 4 + 2][tk][c] + g_xppart[dir * 4 + 3][tk][c];
        g_xdbl[dir][tk][c] = s;
    }
    g_dtr[dir][a_shuf_idx_h(tk, c, 2)] = __float2half((c < DT_RANK) ? s : 0.f);
}

__global__ void out_add_kernel(float* __restrict__ out) {
    int i = blockIdx.x * blockDim.x + threadIdx.x;
    if (i < NTOK * D_MODEL / 4) {
        float4 a = ((const float4*)&g_opart[0][0][0])[i];
        float4 b = ((const float4*)&g_opart[1][0][0])[i];
        a.x += b.x; a.y += b.y; a.z += b.z; a.w += b.w;
        ((float4*)out)[i] = a;
    }
}

// ---------------------------------------------------------------------------
// Depthwise causal conv + bias + SiLU: 8 timesteps/thread, rolling window.
// ---------------------------------------------------------------------------
__global__ void __launch_bounds__(256) conv_silu_kernel(
    const float* __restrict__ w_f, const float* __restrict__ b_f,
    const float* __restrict__ w_r, const float* __restrict__ b_r)
{
    int d  = blockIdx.x * 256 + threadIdx.x;
    int t0 = blockIdx.y * 8;
    int zb = blockIdx.z;
    int dir = zb >> 1, b = zb & 1;

    const float* wsrc = dir ? w_r : w_f;
    float w0 = wsrc[d * D_CONV + 0], w1 = wsrc[d * D_CONV + 1];
    float w2 = wsrc[d * D_CONV + 2], w3 = wsrc[d * D_CONV + 3];
    float bias = (dir ? b_r : b_f)[d];

    int base = dir ? t0 : t0 - 3;
    float xv[11];
#pragma unroll
    for (int j = 0; j < 11; j++) {
        int tt = base + j;
        xv[j] = (tt >= 0 && tt < SEQ) ? g_xz[dir][b * SEQ + tt][d] : 0.f;
    }
#pragma unroll
    for (int i = 0; i < 8; i++) {
        float acc;
        if (dir == 0)
            acc = bias + w0 * xv[i] + w1 * xv[i + 1] + w2 * xv[i + 2] + w3 * xv[i + 3];
        else
            acc = bias + w0 * xv[i + 3] + w1 * xv[i + 2] + w2 * xv[i + 1] + w3 * xv[i];
        float v = siluf(acc);
        int tok = b * SEQ + t0 + i;
        g_xc[dir][tok][d] = v;
        g_xcr[dir][a_shuf_idx_h(tok, d, D_INNER / 64)] = __float2half(v);
    }
}

// ---------------------------------------------------------------------------
// Chunked selective scan (3 kernels).
// ---------------------------------------------------------------------------
__global__ void __launch_bounds__(128) scan_pass1(
    const float* __restrict__ Alog_f, const float* __restrict__ Alog_r)
{
    int dir = blockIdx.z / SCCH;
    int ci  = blockIdx.z % SCCH;
    int b   = blockIdx.y;
    int d   = blockIdx.x * 128 + threadIdx.x;

    float Av[D_STATE];
    bool fast = load_Av(dir ? Alog_r : Alog_f, d, Av);

    __shared__ float sB[SCLEN][D_STATE];
    for (int j = threadIdx.x; j < SCLEN * D_STATE; j += 128) {
        int lt = j >> 4, n = j & 15;
        int gs = ci * SCLEN + lt;
        int t  = dir ? (SEQ - 1 - gs) : gs;
        sB[lt][n] = g_xdbl[dir][b * SEQ + t][DT_RANK + n];
    }
    __syncthreads();

    float h[D_STATE];
#pragma unroll
    for (int n = 0; n < D_STATE; n++) h[n] = 0.f;
    float sdt = 0.f;

    for (int s = 0; s < SCLEN; s++) {
        int gs  = ci * SCLEN + s;
        int t   = dir ? (SEQ - 1 - gs) : gs;
        int tok = b * SEQ + t;
        float dt  = g_dt[dir][tok][d];
        float x   = g_xc[dir][tok][d];
        float dtx = dt * x;
        sdt += dt;
        if (fast) {
            float r = __expf(dt * Av[0]);
            float dA = r;
#pragma unroll
            for (int n = 0; n < D_STATE; n++) {
                h[n] = fmaf(dA, h[n], dtx * sB[s][n]);
                dA *= r;
            }
        } else {
#pragma unroll
            for (int n = 0; n < D_STATE; n++)
                h[n] = fmaf(__expf(dt * Av[n]), h[n], dtx * sB[s][n]);
        }
    }

    g_sdt[dir][b][ci][d] = sdt;
#pragma unroll
    for (int n = 0; n < D_STATE; n++) g_S[dir][b][ci][n][d] = h[n];
}

__global__ void __launch_bounds__(256) scan_prop(
    const float* __restrict__ Alog_f, const float* __restrict__ Alog_r)
{
    int i = blockIdx.x * 256 + threadIdx.x;
    if (i >= 2 * BATCH * D_INNER) return;
    int d   = i % D_INNER;
    int b   = (i / D_INNER) % BATCH;
    int dir = i / (D_INNER * BATCH);

    float Av[D_STATE];
    bool fast = load_Av(dir ? Alog_r : Alog_f, d, Av);

    float h[D_STATE];
#pragma unroll
    for (int n = 0; n < D_STATE; n++) h[n] = 0.f;

    for (int c = 0; c < SCCH; c++) {
#pragma unroll
        for (int n = 0; n < D_STATE; n++) g_hin[dir][b][c][n][d] = h[n];
        float sdt = g_sdt[dir][b][c][d];
        if (fast) {
            float r = __expf(sdt * Av[0]);
            float P = r;
#pragma unroll
            for (int n = 0; n < D_STATE; n++) {
                h[n] = fmaf(P, h[n], g_S[dir][b][c][n][d]);
                P *= r;
            }
        } else {
#pragma unroll
            for (int n = 0; n < D_STATE; n++)
                h[n] = fmaf(__expf(sdt * Av[n]), h[n], g_S[dir][b][c][n][d]);
        }
    }
}

__global__ void __launch_bounds__(128) scan_pass2(
    const float* __restrict__ Alog_f, const float* __restrict__ D_f,
    const float* __restrict__ Alog_r, const float* __restrict__ D_r)
{
    int dir = blockIdx.z / SCCH;
    int ci  = blockIdx.z % SCCH;
    int b   = blockIdx.y;
    int d   = blockIdx.x * 128 + threadIdx.x;

    float Av[D_STATE];
    bool fast = load_Av(dir ? Alog_r : Alog_f, d, Av);
    float Dv = (dir ? D_r : D_f)[d];

    __shared__ float sB[SCLEN][D_STATE];
    __shared__ float sC[SCLEN][D_STATE];
    for (int j = threadIdx.x; j < SCLEN * 2 * D_STATE; j += 128) {
        int lt = j >> 5, cc = j & 31;
        int gs = ci * SCLEN + lt;
        int t  = dir ? (SEQ - 1 - gs) : gs;
        float v = g_xdbl[dir][b * SEQ + t][DT_RANK + cc];
        if (cc < D_STATE) sB[lt][cc] = v;
        else              sC[lt][cc - D_STATE] = v;
    }
    __syncthreads();

    float h[D_STATE];
#pragma unroll
    for (int n = 0; n < D_STATE; n++) h[n] = g_hin[dir][b][ci][n][d];

    for (int s = 0; s < SCLEN; s++) {
        int gs  = ci * SCLEN + s;
        int t   = dir ? (SEQ - 1 - gs) : gs;
        int tok = b * SEQ + t;
        float dt  = g_dt[dir][tok][d];
        float x   = g_xc[dir][tok][d];
        float dtx = dt * x;
        float y = 0.f;
        if (fast) {
            float r = __expf(dt * Av[0]);
            float dA = r;
#pragma unroll
            for (int n = 0; n < D_STATE; n++) {
                h[n] = fmaf(dA, h[n], dtx * sB[s][n]);
                y    = fmaf(h[n], sC[s][n], y);
                dA *= r;
            }
        } else {
#pragma unroll
            for (int n = 0; n < D_STATE; n++) {
                h[n] = fmaf(__expf(dt * Av[n]), h[n], dtx * sB[s][n]);
                y    = fmaf(h[n], sC[s][n], y);
            }
        }
        float z = g_xz[dir][tok][D_INNER + d];
        g_y[dir][a_shuf_idx_h(tok, d, D_INNER / 64)] =
            __float2half((y + x * Dv) * siluf(z));
    }
}

// ---------------------------------------------------------------------------
extern "C" void kernel_launch(void* const* d_in, const int* in_sizes, int n_in,
                              void* d_out, int out_size)
{
    (void)in_sizes; (void)n_in; (void)out_size;

    const float* hidden   = (const float*)d_in[0];
    const float* inW[2]   = {(const float*)d_in[1],  (const float*)d_in[10]};
    const float* convW[2] = {(const float*)d_in[2],  (const float*)d_in[11]};
    const float* convB[2] = {(const float*)d_in[3],  (const float*)d_in[12]};
    const float* xpW[2]   = {(const float*)d_in[4],  (const float*)d_in[13]};
    const float* dtW[2]   = {(const float*)d_in[5],  (const float*)d_in[14]};
    const float* dtB[2]   = {(const float*)d_in[6],  (const float*)d_in[15]};
    const float* Alog[2]  = {(const float*)d_in[7],  (const float*)d_in[16]};
    const float* Dp[2]    = {(const float*)d_in[8],  (const float*)d_in[17]};
    const float* outW[2]  = {(const float*)d_in[9],  (const float*)d_in[18]};
    float* out = (float*)d_out;

    float *xz, *dt, *xpp, *opart;
    __half *xcr, *dtr, *y, *hidr, *inWr, *xpWr, *dtWr, *outWr;
    cudaGetSymbolAddress((void**)&xz,    g_xz);
    cudaGetSymbolAddress((void**)&xcr,   g_xcr);
    cudaGetSymbolAddress((void**)&dtr,   g_dtr);
    cudaGetSymbolAddress((void**)&dt,    g_dt);
    cudaGetSymbolAddress((void**)&y,     g_y);
    cudaGetSymbolAddress((void**)&hidr,  g_hidr);
    cudaGetSymbolAddress((void**)&inWr,  g_inWr);
    cudaGetSymbolAddress((void**)&xpWr,  g_xpWr);
    cudaGetSymbolAddress((void**)&dtWr,  g_dtWr);
    cudaGetSymbolAddress((void**)&outWr, g_outWr);
    cudaGetSymbolAddress((void**)&xpp,   g_xppart);
    cudaGetSymbolAddress((void**)&opart, g_opart);

    cudaFuncSetAttribute(gemm_tc, cudaFuncAttributeMaxDynamicSharedMemorySize, DYN_SMEM);

    const long long szXC   = (long long)NTOK * D_INNER;   // halves (xcr, y)
    const long long szXZ   = (long long)NTOK * 2 * D_INNER;
    const long long szINW  = (long long)2 * D_INNER * D_MODEL;
    const long long szXPW  = (long long)128 * D_INNER;
    const long long szDTW  = (long long)D_INNER * 128;
    const long long szOUTW = (long long)D_MODEL * D_INNER;
    const long long szDTR  = (long long)NTOK * 128;
    const long long szXPP  = (long long)NTOK * XPROJ;
    const long long szOP   = (long long)NTOK * D_MODEL;

    // 0) shuffle+round pre-passes — 3 launches
    {
        int n = NTOK * D_MODEL;
        shufA_k<<<(n + 255) / 256, 256>>>(hidr, hidden, NTOK, D_MODEL);
        n = 2 * D_INNER * D_MODEL;
        shufB2_k<<<(n + 255) / 256, 256>>>(inWr, inW[0], inWr + szINW, inW[1],
                                           2 * D_INNER, 2 * D_INNER, D_MODEL, D_MODEL);
        n = N_XPW + N_OUTW + N_DTW;
        shufW3_k<<<(n + 255) / 256, 256>>>(
            xpWr, xpW[0], xpWr + szXPW, xpW[1],
            outWr, outW[0], outWr + szOUTW, outW[1],
            dtWr, dtW[0], dtWr + szDTW, dtW[1]);
    }

    // 1) in_proj (launch #4 — ncu target): panels=12, nch=12
    gemm_tc<<<dim3((2 * D_INNER) / 128, NTOK / 128, 2), 128, DYN_SMEM>>>(
        hidr, hidr, inWr, inWr + szINW,
        D_MODEL / 64, D_MODEL / 64, 1,
        xz, szXZ, 2 * D_INNER, 2 * D_INNER, nullptr, nullptr, 0);

    // 2) conv + silu
    conv_silu_kernel<<<dim3(D_INNER / 256, SEQ / 8, 4), 256>>>(
        convW[0], convB[0], convW[1], convB[1]);

    // 3) x_proj split-K x4 + reduce: panels=24, nchLoc=6
    gemm_tc<<<dim3(1, NTOK / 128, 8), 128, DYN_SMEM>>>(
        xcr, xcr + szXC, xpWr, xpWr + szXPW,
        D_INNER / 64, D_INNER / 256, 4,
        xpp, szXPP, XPROJ, XPROJ, nullptr, nullptr, 0);
    xp_reduce_kernel<<<(2 * NTOK * 128 + 255) / 256, 256>>>();

    // 4) dt_proj (K pad 128): panels=2, nch=2, softplus+bias
    gemm_tc<<<dim3(D_INNER / 128, NTOK / 128, 2), 128, DYN_SMEM>>>(
        dtr, dtr + szDTR, dtWr, dtWr + szDTW,
        2, 2, 1,
        dt, szXC, D_INNER, D_INNER, dtB[0], dtB[1], 2);

    // 5) chunked selective scan
    scan_pass1<<<dim3(D_INNER / 128, BATCH, 2 * SCCH), 128>>>(Alog[0], Alog[1]);
    scan_prop<<<(2 * BATCH * D_INNER + 255) / 256, 256>>>(Alog[0], Alog[1]);
    scan_pass2<<<dim3(D_INNER / 128, BATCH, 2 * SCCH), 128>>>(
        Alog[0], Dp[0], Alog[1], Dp[1]);

    // 6) out_proj per-dir partials + add: panels=24, nch=24
    gemm_tc<<<dim3(D_MODEL / 128, NTOK / 128, 2), 128, DYN_SMEM>>>(
        y, y + szXC, outWr, outWr + szOUTW,
        D_INNER / 64, D_INNER / 64, 1,
        opart, szOP, D_MODEL, D_MODEL, nullptr, nullptr, 0);
    out_add_kernel<<<(NTOK * D_MODEL / 4 + 255) / 256, 256>>>(out);
}

// round 15
// speedup vs baseline: 1.3336x; 1.0300x over previous
#include <cuda_runtime.h>
#include <cuda_fp16.h>
#include <math.h>
#include <stdint.h>

#define D_MODEL 768
#define D_INNER 1536
#define D_STATE 16
#define D_CONV  4
#define DT_RANK 48
#define BATCH   2
#define SEQ     2048
#define NTOK    (BATCH*SEQ)
#define XPROJ   80
#define SCCH    16
#define SCLEN   (SEQ/SCCH)

#define BK      64
#define NST     3
#define PANEL_H 8192                   // halves per 128x64 panel (16KB)
#define STAGE_B 16384                  // bytes per stage per matrix
#define DYN_SMEM (NST * STAGE_B * 2)   // 96KB -> 2 CTAs/SM

// ---------------- scratch (static device globals; no allocs) ----------------
static __device__ float  g_xz   [2][NTOK][2*D_INNER];
static __device__ float  g_xc   [2][NTOK][D_INNER];
static __device__ __half g_xcr  [2][NTOK*D_INNER];      // A-shuffled fp16
static __device__ float  g_xdbl [2][NTOK][XPROJ];
static __device__ float  g_xppart[8][NTOK][XPROJ];
static __device__ __half g_dtr  [2][NTOK*128];          // A-shuffled, K pad 128
static __device__ float  g_dt   [2][NTOK][D_INNER];
static __device__ __half g_y    [2][NTOK*D_INNER];      // A-shuffled fp16
static __device__ float  g_opart[2][NTOK][D_MODEL];
static __device__ __half g_hidr [NTOK*D_MODEL];
static __device__ __half g_inWr [2][2*D_INNER*D_MODEL];
static __device__ __half g_xpWr [2][128*D_INNER];
static __device__ __half g_dtWr [2][D_INNER*128];
static __device__ __half g_outWr[2][D_MODEL*D_INNER];
// chunked-scan state
static __device__ float g_S  [2][BATCH][SCCH][D_STATE][D_INNER];
static __device__ float g_sdt[2][BATCH][SCCH][D_INNER];

__device__ __forceinline__ float siluf(float v)     { return v / (1.f + __expf(-v)); }
__device__ __forceinline__ float softplusf(float v) { return fmaxf(v, 0.f) + log1pf(__expf(-fabsf(v))); }

// fragment-packed fp16 layouts for mma.m16n8k16 (indices in half units)
__device__ __forceinline__ int a_shuf_idx_h(int row, int k, int panelsTot) {
    int grp = row >> 7, r7 = row & 127, mt = r7 >> 4, r = r7 & 15;
    int p = k >> 6, k6 = k & 63, kt = k6 >> 4, kk = k6 & 15;
    int lane = (r & 7) * 4 + ((kk >> 1) & 3);
    int reg  = ((r >> 3) & 1) + ((kk >> 3) << 1);
    return (grp * panelsTot + p) * PANEL_H + (mt * 4 + kt) * 256 + lane * 8 + reg * 2 + (kk & 1);
}
__device__ __forceinline__ int b_shuf_idx_h(int n, int k, int panelsTot) {
    int grp = n >> 7, n7 = n & 127, nt = n7 >> 3, nn = n7 & 7;
    int p = k >> 6, k6 = k & 63, kt = k6 >> 4, kk = k6 & 15;
    int lane = nn * 4 + ((kk >> 1) & 3);
    int reg  = kk >> 3;
    return (grp * panelsTot + p) * PANEL_H + (nt * 4 + kt) * 128 + lane * 4 + reg * 2 + (kk & 1);
}
__device__ __forceinline__ uint32_t smem_u32(const void* p) {
    uint32_t a;
    asm("{ .reg .u64 t; cvta.to.shared.u64 t, %1; cvt.u32.u64 %0, t; }" : "=r"(a) : "l"(p));
    return a;
}
__device__ __forceinline__ void cpasync16(uint32_t dst, const void* src) {
    asm volatile("cp.async.cg.shared.global [%0], [%1], 16;"
                 :: "r"(dst), "l"(src) : "memory");
}
#define CP_COMMIT() asm volatile("cp.async.commit_group;" ::: "memory")
#define CP_WAIT1()  asm volatile("cp.async.wait_group 1;" ::: "memory")

__device__ __forceinline__ void mma16h(float* d, const uint32_t* a, const uint32_t* b) {
    asm volatile(
        "mma.sync.aligned.m16n8k16.row.col.f32.f16.f16.f32 "
        "{%0,%1,%2,%3}, {%4,%5,%6,%7}, {%8,%9}, {%0,%1,%2,%3};"
        : "+f"(d[0]), "+f"(d[1]), "+f"(d[2]), "+f"(d[3])
        : "r"(a[0]), "r"(a[1]), "r"(a[2]), "r"(a[3]), "r"(b[0]), "r"(b[1]));
}

// load Av and check geometric structure A_n = n*A_1
__device__ __forceinline__ bool load_Av(const float* Alog, int d, float* Av) {
    bool fast = true;
#pragma unroll
    for (int n = 0; n < D_STATE; n++) {
        Av[n] = -__expf(Alog[d * D_STATE + n]);
        fast = fast && (fabsf(Av[n] - (n + 1) * Av[0]) <= 1e-3f * fabsf(Av[n]) + 1e-9f);
    }
    return fast;
}

// ---------------------------------------------------------------------------
// fp16 GEMM (m16n8k16), fragment-shuffled operands. 128x128 CTA tile, BK=64,
// 64x64 warp tile (4 warps), 3-stage cp.async, ks-software-pipelined frags.
// z: dir = z/zDiv, split = z%zDiv. mode 0: store; 2: softplus(v + bias[n]).
// ---------------------------------------------------------------------------
__global__ void __launch_bounds__(128, 2) gemm_tc(
    const __half* A0, const __half* A1,
    const __half* B0, const __half* B1,
    int panelsTot, int nchLoc, int zDiv,
    float* C, long long cZStride, int ldc, int Nfull,
    const float* bias0, const float* bias1, int mode)
{
    extern __shared__ __half hsm[];
    const uint32_t aA = smem_u32(hsm);
    const uint32_t aB = aA + NST * STAGE_B;

    const int tid    = threadIdx.x;
    const int lane   = tid & 31;
    const int wid    = tid >> 5;
    const int warp_m = wid & 1;
    const int warp_n = wid >> 1;
    const int g      = lane >> 2;
    const int t      = lane & 3;
    const int z      = blockIdx.z;
    const int dir    = z / zDiv;
    const int split  = z - dir * zDiv;
    const int bm     = blockIdx.y * 128;
    const int bn     = blockIdx.x * 128;

    const __half* A = (dir ? A1 : A0)
        + (size_t)((bm >> 7) * panelsTot + split * nchLoc) * PANEL_H;
    const __half* B = (dir ? B1 : B0)
        + (size_t)((bn >> 7) * panelsTot + split * nchLoc) * PANEL_H;
    const float* bias = dir ? bias1 : bias0;
    float* Cz = C + (long long)z * cZStride;

    // producer: 8x16B per matrix per thread per chunk (pure linear copy)
    const __half* pA = A + tid * 8;
    const __half* pB = B + tid * 8;
    const uint32_t soff = (uint32_t)tid * 16;
    uint32_t stWr = 0;
    auto issue = [&]() {
#pragma unroll
        for (int i = 0; i < 8; i++) {
            cpasync16(aA + stWr + soff + i * 2048, pA + i * 1024);
            cpasync16(aB + stWr + soff + i * 2048, pB + i * 1024);
        }
        CP_COMMIT();
        pA += PANEL_H; pB += PANEL_H;
        stWr += STAGE_B;
        if (stWr == NST * STAGE_B) stWr = 0;
    };

    float acc[4][8][4];
#pragma unroll
    for (int mi = 0; mi < 4; mi++)
#pragma unroll
        for (int ni = 0; ni < 8; ni++)
#pragma unroll
            for (int r = 0; r < 4; r++) acc[mi][ni][r] = 0.f;

    issue();
    issue();

    uint32_t stRd = 0;
    for (int c = 0; c < nchLoc; c++) {
        CP_WAIT1();
        __syncthreads();
        if (c + NST - 1 < nchLoc) issue();
        else                      CP_COMMIT();

        const __half* A_ = hsm + (stRd >> 1);
        const __half* B_ = A_ + NST * PANEL_H;
        stRd += STAGE_B;
        if (stRd == NST * STAGE_B) stRd = 0;

        // ks software pipeline: double-buffered fragment registers
        uint4 af[2][4];
        uint2 bf[2][8];
#pragma unroll
        for (int mi = 0; mi < 4; mi++)
            af[0][mi] = *(const uint4*)(A_ + ((warp_m * 4 + mi) * 4 + 0) * 256 + lane * 8);
#pragma unroll
        for (int ni = 0; ni < 8; ni++)
            bf[0][ni] = *(const uint2*)(B_ + ((warp_n * 8 + ni) * 4 + 0) * 128 + lane * 4);

#pragma unroll
        for (int ks = 0; ks < 4; ks++) {
            const int cb = ks & 1, nb = cb ^ 1;
            if (ks < 3) {
#pragma unroll
                for (int mi = 0; mi < 4; mi++)
                    af[nb][mi] = *(const uint4*)(A_ + ((warp_m * 4 + mi) * 4 + ks + 1) * 256 + lane * 8);
#pragma unroll
                for (int ni = 0; ni < 8; ni++)
                    bf[nb][ni] = *(const uint2*)(B_ + ((warp_n * 8 + ni) * 4 + ks + 1) * 128 + lane * 4);
            }
#pragma unroll
            for (int mi = 0; mi < 4; mi++) {
                uint32_t au[4] = { af[cb][mi].x, af[cb][mi].y, af[cb][mi].z, af[cb][mi].w };
#pragma unroll
                for (int ni = 0; ni < 8; ni++) {
                    uint32_t bu[2] = { bf[cb][ni].x, bf[cb][ni].y };
                    mma16h(acc[mi][ni], au, bu);
                }
            }
        }
    }

#pragma unroll
    for (int mi = 0; mi < 4; mi++) {
        int row = bm + warp_m * 64 + mi * 16 + g;
#pragma unroll
        for (int ni = 0; ni < 8; ni++) {
            int col = bn + warp_n * 64 + ni * 8 + t * 2;
            if (col < Nfull) {
                float v00 = acc[mi][ni][0], v01 = acc[mi][ni][1];
                float v10 = acc[mi][ni][2], v11 = acc[mi][ni][3];
                if (mode == 2) {
                    float b0 = bias[col], b1 = bias[col + 1];
                    v00 = softplusf(v00 + b0); v01 = softplusf(v01 + b1);
                    v10 = softplusf(v10 + b0); v11 = softplusf(v11 + b1);
                }
                *(float2*)(Cz + (size_t)row * ldc + col)       = make_float2(v00, v01);
                *(float2*)(Cz + (size_t)(row + 8) * ldc + col) = make_float2(v10, v11);
            }
        }
    }
}

// ---------------------------------------------------------------------------
// Shuffle pre-passes (3 launches; in_proj gemm is launch #4 for ncu)
// ---------------------------------------------------------------------------
__global__ void shufA_k(__half* __restrict__ dst, const float* __restrict__ src,
                        int rows, int K) {
    int i = blockIdx.x * blockDim.x + threadIdx.x;
    if (i < rows * K) {
        int row = i / K, k = i - row * K;
        dst[a_shuf_idx_h(row, k, K >> 6)] = __float2half(src[i]);
    }
}
__global__ void shufB2_k(__half* __restrict__ d0, const float* __restrict__ s0,
                         __half* __restrict__ d1, const float* __restrict__ s1,
                         int rows, int rowsPad, int Kin, int Kpad) {
    int i = blockIdx.x * blockDim.x + threadIdx.x;
    if (i < rowsPad * Kpad) {
        int row = i / Kpad, k = i - row * Kpad;
        int idx = b_shuf_idx_h(row, k, Kpad >> 6);
        bool ok = (row < rows) && (k < Kin);
        d0[idx] = __float2half(ok ? s0[row * Kin + k] : 0.f);
        d1[idx] = __float2half(ok ? s1[row * Kin + k] : 0.f);
    }
}
#define N_XPW  (128 * D_INNER)
#define N_OUTW (D_MODEL * D_INNER)
#define N_DTW  (D_INNER * 128)
__global__ void shufW3_k(
    __half* __restrict__ xd0, const float* __restrict__ xs0,
    __half* __restrict__ xd1, const float* __restrict__ xs1,
    __half* __restrict__ od0, const float* __restrict__ os0,
    __half* __restrict__ od1, const float* __restrict__ os1,
    __half* __restrict__ dd0, const float* __restrict__ ds0,
    __half* __restrict__ dd1, const float* __restrict__ ds1)
{
    int i = blockIdx.x * blockDim.x + threadIdx.x;
    if (i < N_XPW) {
        int row = i / D_INNER, k = i - row * D_INNER;
        int idx = b_shuf_idx_h(row, k, D_INNER >> 6);
        bool ok = row < XPROJ;
        xd0[idx] = __float2half(ok ? xs0[row * D_INNER + k] : 0.f);
        xd1[idx] = __float2half(ok ? xs1[row * D_INNER + k] : 0.f);
    } else if (i < N_XPW + N_OUTW) {
        int j = i - N_XPW;
        int row = j / D_INNER, k = j - row * D_INNER;
        int idx = b_shuf_idx_h(row, k, D_INNER >> 6);
        od0[idx] = __float2half(os0[row * D_INNER + k]);
        od1[idx] = __float2half(os1[row * D_INNER + k]);
    } else if (i < N_XPW + N_OUTW + N_DTW) {
        int j = i - N_XPW - N_OUTW;
        int row = j >> 7, k = j & 127;
        int idx = b_shuf_idx_h(row, k, 2);
        bool ok = k < DT_RANK;
        dd0[idx] = __float2half(ok ? ds0[row * DT_RANK + k] : 0.f);
        dd1[idx] = __float2half(ok ? ds1[row * DT_RANK + k] : 0.f);
    }
}

// x_proj split-K reduce: xdbl exact + dtr (A-shuffled fp16, K pad 128)
__global__ void xp_reduce_kernel() {
    int i = blockIdx.x * blockDim.x + threadIdx.x;   // 2*NTOK*128
    if (i >= 2 * NTOK * 128) return;
    int c   = i & 127;
    int tk  = (i >> 7) % NTOK;
    int dir = i / (128 * NTOK);
    float s = 0.f;
    if (c < XPROJ) {
        s = g_xppart[dir * 4 + 0][tk][c] + g_xppart[dir * 4 + 1][tk][c]
          + g_xppart[dir * 4 + 2][tk][c] + g_xppart[dir * 4 + 3][tk][c];
        g_xdbl[dir][tk][c] = s;
    }
    g_dtr[dir][a_shuf_idx_h(tk, c, 2)] = __float2half((c < DT_RANK) ? s : 0.f);
}

__global__ void out_add_kernel(float* __restrict__ out) {
    int i = blockIdx.x * blockDim.x + threadIdx.x;
    if (i < NTOK * D_MODEL / 4) {
        float4 a = ((const float4*)&g_opart[0][0][0])[i];
        float4 b = ((const float4*)&g_opart[1][0][0])[i];
        a.x += b.x; a.y += b.y; a.z += b.z; a.w += b.w;
        ((float4*)out)[i] = a;
    }
}

// ---------------------------------------------------------------------------
// Depthwise causal conv + bias + SiLU: 8 timesteps/thread, rolling window.
// ---------------------------------------------------------------------------
__global__ void __launch_bounds__(256) conv_silu_kernel(
    const float* __restrict__ w_f, const float* __restrict__ b_f,
    const float* __restrict__ w_r, const float* __restrict__ b_r)
{
    int d  = blockIdx.x * 256 + threadIdx.x;
    int t0 = blockIdx.y * 8;
    int zb = blockIdx.z;
    int dir = zb >> 1, b = zb & 1;

    const float* wsrc = dir ? w_r : w_f;
    float w0 = wsrc[d * D_CONV + 0], w1 = wsrc[d * D_CONV + 1];
    float w2 = wsrc[d * D_CONV + 2], w3 = wsrc[d * D_CONV + 3];
    float bias = (dir ? b_r : b_f)[d];

    int base = dir ? t0 : t0 - 3;
    float xv[11];
#pragma unroll
    for (int j = 0; j < 11; j++) {
        int tt = base + j;
        xv[j] = (tt >= 0 && tt < SEQ) ? g_xz[dir][b * SEQ + tt][d] : 0.f;
    }
#pragma unroll
    for (int i = 0; i < 8; i++) {
        float acc;
        if (dir == 0)
            acc = bias + w0 * xv[i] + w1 * xv[i + 1] + w2 * xv[i + 2] + w3 * xv[i + 3];
        else
            acc = bias + w0 * xv[i + 3] + w1 * xv[i + 2] + w2 * xv[i + 1] + w3 * xv[i];
        float v = siluf(acc);
        int tok = b * SEQ + t0 + i;
        g_xc[dir][tok][d] = v;
        g_xcr[dir][a_shuf_idx_h(tok, d, D_INNER / 64)] = __float2half(v);
    }
}

// ---------------------------------------------------------------------------
// Chunked selective scan (2 kernels; chunk-state chain folded into pass2).
// ---------------------------------------------------------------------------
__global__ void __launch_bounds__(128) scan_pass1(
    const float* __restrict__ Alog_f, const float* __restrict__ Alog_r)
{
    int dir = blockIdx.z / SCCH;
    int ci  = blockIdx.z % SCCH;
    int b   = blockIdx.y;
    int d   = blockIdx.x * 128 + threadIdx.x;

    float Av[D_STATE];
    bool fast = load_Av(dir ? Alog_r : Alog_f, d, Av);

    __shared__ float sB[SCLEN][D_STATE];
    for (int j = threadIdx.x; j < SCLEN * D_STATE; j += 128) {
        int lt = j >> 4, n = j & 15;
        int gs = ci * SCLEN + lt;
        int t  = dir ? (SEQ - 1 - gs) : gs;
        sB[lt][n] = g_xdbl[dir][b * SEQ + t][DT_RANK + n];
    }
    __syncthreads();

    float h[D_STATE];
#pragma unroll
    for (int n = 0; n < D_STATE; n++) h[n] = 0.f;
    float sdt = 0.f;

    for (int s = 0; s < SCLEN; s++) {
        int gs  = ci * SCLEN + s;
        int t   = dir ? (SEQ - 1 - gs) : gs;
        int tok = b * SEQ + t;
        float dt  = g_dt[dir][tok][d];
        float x   = g_xc[dir][tok][d];
        float dtx = dt * x;
        sdt += dt;
        if (fast) {
            float r = __expf(dt * Av[0]);
            float dA = r;
#pragma unroll
            for (int n = 0; n < D_STATE; n++) {
                h[n] = fmaf(dA, h[n], dtx * sB[s][n]);
                dA *= r;
            }
        } else {
#pragma unroll
            for (int n = 0; n < D_STATE; n++)
                h[n] = fmaf(__expf(dt * Av[n]), h[n], dtx * sB[s][n]);
        }
    }

    g_sdt[dir][b][ci][d] = sdt;
#pragma unroll
    for (int n = 0; n < D_STATE; n++) g_S[dir][b][ci][n][d] = h[n];
}

__global__ void __launch_bounds__(128) scan_pass2(
    const float* __restrict__ Alog_f, const float* __restrict__ D_f,
    const float* __restrict__ Alog_r, const float* __restrict__ D_r)
{
    int dir = blockIdx.z / SCCH;
    int ci  = blockIdx.z % SCCH;
    int b   = blockIdx.y;
    int d   = blockIdx.x * 128 + threadIdx.x;

    float Av[D_STATE];
    bool fast = load_Av(dir ? Alog_r : Alog_f, d, Av);
    float Dv = (dir ? D_r : D_f)[d];

    __shared__ float sB[SCLEN][D_STATE];
    __shared__ float sC[SCLEN][D_STATE];
    for (int j = threadIdx.x; j < SCLEN * 2 * D_STATE; j += 128) {
        int lt = j >> 5, cc = j & 31;
        int gs = ci * SCLEN + lt;
        int t  = dir ? (SEQ - 1 - gs) : gs;
        float v = g_xdbl[dir][b * SEQ + t][DT_RANK + cc];
        if (cc < D_STATE) sB[lt][cc] = v;
        else              sC[lt][cc - D_STATE] = v;
    }
    __syncthreads();

    // chain chunk states 0..ci-1 (was scan_prop)
    float h[D_STATE];
#pragma unroll
    for (int n = 0; n < D_STATE; n++) h[n] = 0.f;
    for (int c = 0; c < ci; c++) {
        float sdt = g_sdt[dir][b][c][d];
        if (fast) {
            float r = __expf(sdt * Av[0]);
            float P = r;
#pragma unroll
            for (int n = 0; n < D_STATE; n++) {
                h[n] = fmaf(P, h[n], g_S[dir][b][c][n][d]);
                P *= r;
            }
        } else {
#pragma unroll
            for (int n = 0; n < D_STATE; n++)
                h[n] = fmaf(__expf(sdt * Av[n]), h[n], g_S[dir][b][c][n][d]);
        }
    }

    for (int s = 0; s < SCLEN; s++) {
        int gs  = ci * SCLEN + s;
        int t   = dir ? (SEQ - 1 - gs) : gs;
        int tok = b * SEQ + t;
        float dt  = g_dt[dir][tok][d];
        float x   = g_xc[dir][tok][d];
        float dtx = dt * x;
        float y = 0.f;
        if (fast) {
            float r = __expf(dt * Av[0]);
            float dA = r;
#pragma unroll
            for (int n = 0; n < D_STATE; n++) {
                h[n] = fmaf(dA, h[n], dtx * sB[s][n]);
                y    = fmaf(h[n], sC[s][n], y);
                dA *= r;
            }
        } else {
#pragma unroll
            for (int n = 0; n < D_STATE; n++) {
                h[n] = fmaf(__expf(dt * Av[n]), h[n], dtx * sB[s][n]);
                y    = fmaf(h[n], sC[s][n], y);
            }
        }
        float z = g_xz[dir][tok][D_INNER + d];
        g_y[dir][a_shuf_idx_h(tok, d, D_INNER / 64)] =
            __float2half((y + x * Dv) * siluf(z));
    }
}

// ---------------------------------------------------------------------------
extern "C" void kernel_launch(void* const* d_in, const int* in_sizes, int n_in,
                              void* d_out, int out_size)
{
    (void)in_sizes; (void)n_in; (void)out_size;

    const float* hidden   = (const float*)d_in[0];
    const float* inW[2]   = {(const float*)d_in[1],  (const float*)d_in[10]};
    const float* convW[2] = {(const float*)d_in[2],  (const float*)d_in[11]};
    const float* convB[2] = {(const float*)d_in[3],  (const float*)d_in[12]};
    const float* xpW[2]   = {(const float*)d_in[4],  (const float*)d_in[13]};
    const float* dtW[2]   = {(const float*)d_in[5],  (const float*)d_in[14]};
    const float* dtB[2]   = {(const float*)d_in[6],  (const float*)d_in[15]};
    const float* Alog[2]  = {(const float*)d_in[7],  (const float*)d_in[16]};
    const float* Dp[2]    = {(const float*)d_in[8],  (const float*)d_in[17]};
    const float* outW[2]  = {(const float*)d_in[9],  (const float*)d_in[18]};
    float* out = (float*)d_out;

    float *xz, *dt, *xpp, *opart;
    __half *xcr, *dtr, *y, *hidr, *inWr, *xpWr, *dtWr, *outWr;
    cudaGetSymbolAddress((void**)&xz,    g_xz);
    cudaGetSymbolAddress((void**)&xcr,   g_xcr);
    cudaGetSymbolAddress((void**)&dtr,   g_dtr);
    cudaGetSymbolAddress((void**)&dt,    g_dt);
    cudaGetSymbolAddress((void**)&y,     g_y);
    cudaGetSymbolAddress((void**)&hidr,  g_hidr);
    cudaGetSymbolAddress((void**)&inWr,  g_inWr);
    cudaGetSymbolAddress((void**)&xpWr,  g_xpWr);
    cudaGetSymbolAddress((void**)&dtWr,  g_dtWr);
    cudaGetSymbolAddress((void**)&outWr, g_outWr);
    cudaGetSymbolAddress((void**)&xpp,   g_xppart);
    cudaGetSymbolAddress((void**)&opart, g_opart);

    cudaFuncSetAttribute(gemm_tc, cudaFuncAttributeMaxDynamicSharedMemorySize, DYN_SMEM);

    const long long szXC   = (long long)NTOK * D_INNER;   // halves (xcr, y)
    const long long szXZ   = (long long)NTOK * 2 * D_INNER;
    const long long szINW  = (long long)2 * D_INNER * D_MODEL;
    const long long szXPW  = (long long)128 * D_INNER;
    const long long szDTW  = (long long)D_INNER * 128;
    const long long szOUTW = (long long)D_MODEL * D_INNER;
    const long long szDTR  = (long long)NTOK * 128;
    const long long szXPP  = (long long)NTOK * XPROJ;
    const long long szOP   = (long long)NTOK * D_MODEL;

    // 0) shuffle+round pre-passes — 3 launches
    {
        int n = NTOK * D_MODEL;
        shufA_k<<<(n + 255) / 256, 256>>>(hidr, hidden, NTOK, D_MODEL);
        n = 2 * D_INNER * D_MODEL;
        shufB2_k<<<(n + 255) / 256, 256>>>(inWr, inW[0], inWr + szINW, inW[1],
                                           2 * D_INNER, 2 * D_INNER, D_MODEL, D_MODEL);
        n = N_XPW + N_OUTW + N_DTW;
        shufW3_k<<<(n + 255) / 256, 256>>>(
            xpWr, xpW[0], xpWr + szXPW, xpW[1],
            outWr, outW[0], outWr + szOUTW, outW[1],
            dtWr, dtW[0], dtWr + szDTW, dtW[1]);
    }

    // 1) in_proj (launch #4 — ncu target): panels=12, nch=12
    gemm_tc<<<dim3((2 * D_INNER) / 128, NTOK / 128, 2), 128, DYN_SMEM>>>(
        hidr, hidr, inWr, inWr + szINW,
        D_MODEL / 64, D_MODEL / 64, 1,
        xz, szXZ, 2 * D_INNER, 2 * D_INNER, nullptr, nullptr, 0);

    // 2) conv + silu
    conv_silu_kernel<<<dim3(D_INNER / 256, SEQ / 8, 4), 256>>>(
        convW[0], convB[0], convW[1], convB[1]);

    // 3) x_proj split-K x4 + reduce: panels=24, nchLoc=6
    gemm_tc<<<dim3(1, NTOK / 128, 8), 128, DYN_SMEM>>>(
        xcr, xcr + szXC, xpWr, xpWr + szXPW,
        D_INNER / 64, D_INNER / 256, 4,
        xpp, szXPP, XPROJ, XPROJ, nullptr, nullptr, 0);
    xp_reduce_kernel<<<(2 * NTOK * 128 + 255) / 256, 256>>>();

    // 4) dt_proj (K pad 128): panels=2, nch=2, softplus+bias
    gemm_tc<<<dim3(D_INNER / 128, NTOK / 128, 2), 128, DYN_SMEM>>>(
        dtr, dtr + szDTR, dtWr, dtWr + szDTW,
        2, 2, 1,
        dt, szXC, D_INNER, D_INNER, dtB[0], dtB[1], 2);

    // 5) chunked selective scan (prop folded into pass2)
    scan_pass1<<<dim3(D_INNER / 128, BATCH, 2 * SCCH), 128>>>(Alog[0], Alog[1]);
    scan_pass2<<<dim3(D_INNER / 128, BATCH, 2 * SCCH), 128>>>(
        Alog[0], Dp[0], Alog[1], Dp[1]);

    // 6) out_proj per-dir partials + add: panels=24, nch=24
    gemm_tc<<<dim3(D_MODEL / 128, NTOK / 128, 2), 128, DYN_SMEM>>>(
        y, y + szXC, outWr, outWr + szOUTW,
        D_INNER / 64, D_INNER / 64, 1,
        opart, szOP, D_MODEL, D_MODEL, nullptr, nullptr, 0);
    out_add_kernel<<<(NTOK * D_MODEL / 4 + 255) / 256, 256>>>(out);
}

// round 16
// speedup vs baseline: 1.3443x; 1.0080x over previous
#include <cuda_runtime.h>
#include <cuda_fp16.h>
#include <math.h>
#include <stdint.h>

#define D_MODEL 768
#define D_INNER 1536
#define D_STATE 16
#define D_CONV  4
#define DT_RANK 48
#define BATCH   2
#define SEQ     2048
#define NTOK    (BATCH*SEQ)
#define XPROJ   80
#define SCCH    16
#define SCLEN   (SEQ/SCCH)

#define BK      64
#define NST     3
#define PANEL_H 8192                   // halves per 128x64 panel (16KB)
#define STAGE_B 16384                  // bytes per stage per matrix
#define DYN_SMEM (NST * STAGE_B * 2)   // 96KB -> 2 CTAs/SM

// ---------------- scratch (static device globals; no allocs) ----------------
static __device__ float  g_xz   [2][NTOK][2*D_INNER];
static __device__ float  g_xc   [2][NTOK][D_INNER];
static __device__ __half g_xcr  [2][NTOK*D_INNER];      // A-shuffled fp16
static __device__ float  g_xdbl [2][NTOK][XPROJ];
static __device__ float  g_xppart[8][NTOK][XPROJ];
static __device__ __half g_dtr  [2][NTOK*64 + PANEL_H]; // A-shuffled, K pad 64 (+slack for prologue overread)
static __device__ float  g_dt   [2][NTOK][D_INNER];
static __device__ __half g_y    [2][NTOK*D_INNER];      // A-shuffled fp16
static __device__ float  g_opart[4][NTOK][D_MODEL];     // out_proj: 2 dirs x 2 K-splits
static __device__ __half g_hidr [NTOK*D_MODEL];
static __device__ __half g_inWr [2][2*D_INNER*D_MODEL];
static __device__ __half g_xpWr [2][128*D_INNER];
static __device__ __half g_dtWr [2][D_INNER*64 + PANEL_H];
static __device__ __half g_outWr[2][D_MODEL*D_INNER];
// chunked-scan state
static __device__ float g_S  [2][BATCH][SCCH][D_STATE][D_INNER];
static __device__ float g_sdt[2][BATCH][SCCH][D_INNER];

__device__ __forceinline__ float siluf(float v)     { return v / (1.f + __expf(-v)); }
__device__ __forceinline__ float softplusf(float v) { return fmaxf(v, 0.f) + log1pf(__expf(-fabsf(v))); }

// fragment-packed fp16 layouts for mma.m16n8k16 (indices in half units)
__device__ __forceinline__ int a_shuf_idx_h(int row, int k, int panelsTot) {
    int grp = row >> 7, r7 = row & 127, mt = r7 >> 4, r = r7 & 15;
    int p = k >> 6, k6 = k & 63, kt = k6 >> 4, kk = k6 & 15;
    int lane = (r & 7) * 4 + ((kk >> 1) & 3);
    int reg  = ((r >> 3) & 1) + ((kk >> 3) << 1);
    return (grp * panelsTot + p) * PANEL_H + (mt * 4 + kt) * 256 + lane * 8 + reg * 2 + (kk & 1);
}
__device__ __forceinline__ int b_shuf_idx_h(int n, int k, int panelsTot) {
    int grp = n >> 7, n7 = n & 127, nt = n7 >> 3, nn = n7 & 7;
    int p = k >> 6, k6 = k & 63, kt = k6 >> 4, kk = k6 & 15;
    int lane = nn * 4 + ((kk >> 1) & 3);
    int reg  = kk >> 3;
    return (grp * panelsTot + p) * PANEL_H + (nt * 4 + kt) * 128 + lane * 4 + reg * 2 + (kk & 1);
}
__device__ __forceinline__ uint32_t smem_u32(const void* p) {
    uint32_t a;
    asm("{ .reg .u64 t; cvta.to.shared.u64 t, %1; cvt.u32.u64 %0, t; }" : "=r"(a) : "l"(p));
    return a;
}
__device__ __forceinline__ void cpasync16(uint32_t dst, const void* src) {
    asm volatile("cp.async.cg.shared.global [%0], [%1], 16;"
                 :: "r"(dst), "l"(src) : "memory");
}
#define CP_COMMIT() asm volatile("cp.async.commit_group;" ::: "memory")
#define CP_WAIT1()  asm volatile("cp.async.wait_group 1;" ::: "memory")

__device__ __forceinline__ void mma16h(float* d, const uint32_t* a, const uint32_t* b) {
    asm volatile(
        "mma.sync.aligned.m16n8k16.row.col.f32.f16.f16.f32 "
        "{%0,%1,%2,%3}, {%4,%5,%6,%7}, {%8,%9}, {%0,%1,%2,%3};"
        : "+f"(d[0]), "+f"(d[1]), "+f"(d[2]), "+f"(d[3])
        : "r"(a[0]), "r"(a[1]), "r"(a[2]), "r"(a[3]), "r"(b[0]), "r"(b[1]));
}

// load Av and check geometric structure A_n = n*A_1
__device__ __forceinline__ bool load_Av(const float* Alog, int d, float* Av) {
    bool fast = true;
#pragma unroll
    for (int n = 0; n < D_STATE; n++) {
        Av[n] = -__expf(Alog[d * D_STATE + n]);
        fast = fast && (fabsf(Av[n] - (n + 1) * Av[0]) <= 1e-3f * fabsf(Av[n]) + 1e-9f);
    }
    return fast;
}

// ---------------------------------------------------------------------------
// fp16 GEMM (m16n8k16), fragment-shuffled operands. 128x128 CTA tile, BK=64,
// 64x64 warp tile (4 warps), 3-stage cp.async, ks-software-pipelined frags.
// z: dir = z/zDiv, split = z%zDiv. mode 0: store; 2: softplus(v + bias[n]).
// NOTE: prologue issues 2 chunks; callers with nchLoc==1 must provide
// one panel of slack after the last row-group (never consumed).
// ---------------------------------------------------------------------------
__global__ void __launch_bounds__(128, 2) gemm_tc(
    const __half* A0, const __half* A1,
    const __half* B0, const __half* B1,
    int panelsTot, int nchLoc, int zDiv,
    float* C, long long cZStride, int ldc, int Nfull,
    const float* bias0, const float* bias1, int mode)
{
    extern __shared__ __half hsm[];
    const uint32_t aA = smem_u32(hsm);
    const uint32_t aB = aA + NST * STAGE_B;

    const int tid    = threadIdx.x;
    const int lane   = tid & 31;
    const int wid    = tid >> 5;
    const int warp_m = wid & 1;
    const int warp_n = wid >> 1;
    const int g      = lane >> 2;
    const int t      = lane & 3;
    const int z      = blockIdx.z;
    const int dir    = z / zDiv;
    const int split  = z - dir * zDiv;
    const int bm     = blockIdx.y * 128;
    const int bn     = blockIdx.x * 128;

    const __half* A = (dir ? A1 : A0)
        + (size_t)((bm >> 7) * panelsTot + split * nchLoc) * PANEL_H;
    const __half* B = (dir ? B1 : B0)
        + (size_t)((bn >> 7) * panelsTot + split * nchLoc) * PANEL_H;
    const float* bias = dir ? bias1 : bias0;
    float* Cz = C + (long long)z * cZStride;

    // producer: 8x16B per matrix per thread per chunk (pure linear copy)
    const __half* pA = A + tid * 8;
    const __half* pB = B + tid * 8;
    const uint32_t soff = (uint32_t)tid * 16;
    uint32_t stWr = 0;
    auto issue = [&]() {
#pragma unroll
        for (int i = 0; i < 8; i++) {
            cpasync16(aA + stWr + soff + i * 2048, pA + i * 1024);
            cpasync16(aB + stWr + soff + i * 2048, pB + i * 1024);
        }
        CP_COMMIT();
        pA += PANEL_H; pB += PANEL_H;
        stWr += STAGE_B;
        if (stWr == NST * STAGE_B) stWr = 0;
    };

    float acc[4][8][4];
#pragma unroll
    for (int mi = 0; mi < 4; mi++)
#pragma unroll
        for (int ni = 0; ni < 8; ni++)
#pragma unroll
            for (int r = 0; r < 4; r++) acc[mi][ni][r] = 0.f;

    issue();
    issue();

    uint32_t stRd = 0;
    for (int c = 0; c < nchLoc; c++) {
        CP_WAIT1();
        __syncthreads();
        if (c + NST - 1 < nchLoc) issue();
        else                      CP_COMMIT();

        const __half* A_ = hsm + (stRd >> 1);
        const __half* B_ = A_ + NST * PANEL_H;
        stRd += STAGE_B;
        if (stRd == NST * STAGE_B) stRd = 0;

        // ks software pipeline: double-buffered fragment registers
        uint4 af[2][4];
        uint2 bf[2][8];
#pragma unroll
        for (int mi = 0; mi < 4; mi++)
            af[0][mi] = *(const uint4*)(A_ + ((warp_m * 4 + mi) * 4 + 0) * 256 + lane * 8);
#pragma unroll
        for (int ni = 0; ni < 8; ni++)
            bf[0][ni] = *(const uint2*)(B_ + ((warp_n * 8 + ni) * 4 + 0) * 128 + lane * 4);

#pragma unroll
        for (int ks = 0; ks < 4; ks++) {
            const int cb = ks & 1, nb = cb ^ 1;
            if (ks < 3) {
#pragma unroll
                for (int mi = 0; mi < 4; mi++)
                    af[nb][mi] = *(const uint4*)(A_ + ((warp_m * 4 + mi) * 4 + ks + 1) * 256 + lane * 8);
#pragma unroll
                for (int ni = 0; ni < 8; ni++)
                    bf[nb][ni] = *(const uint2*)(B_ + ((warp_n * 8 + ni) * 4 + ks + 1) * 128 + lane * 4);
            }
#pragma unroll
            for (int mi = 0; mi < 4; mi++) {
                uint32_t au[4] = { af[cb][mi].x, af[cb][mi].y, af[cb][mi].z, af[cb][mi].w };
#pragma unroll
                for (int ni = 0; ni < 8; ni++) {
                    uint32_t bu[2] = { bf[cb][ni].x, bf[cb][ni].y };
                    mma16h(acc[mi][ni], au, bu);
                }
            }
        }
    }

#pragma unroll
    for (int mi = 0; mi < 4; mi++) {
        int row = bm + warp_m * 64 + mi * 16 + g;
#pragma unroll
        for (int ni = 0; ni < 8; ni++) {
            int col = bn + warp_n * 64 + ni * 8 + t * 2;
            if (col < Nfull) {
                float v00 = acc[mi][ni][0], v01 = acc[mi][ni][1];
                float v10 = acc[mi][ni][2], v11 = acc[mi][ni][3];
                if (mode == 2) {
                    float b0 = bias[col], b1 = bias[col + 1];
                    v00 = softplusf(v00 + b0); v01 = softplusf(v01 + b1);
                    v10 = softplusf(v10 + b0); v11 = softplusf(v11 + b1);
                }
                *(float2*)(Cz + (size_t)row * ldc + col)       = make_float2(v00, v01);
                *(float2*)(Cz + (size_t)(row + 8) * ldc + col) = make_float2(v10, v11);
            }
        }
    }
}

// ---------------------------------------------------------------------------
// Shuffle pre-passes (3 launches; in_proj gemm is launch #4 for ncu)
// ---------------------------------------------------------------------------
__global__ void shufA_k(__half* __restrict__ dst, const float* __restrict__ src,
                        int rows, int K) {
    int i = blockIdx.x * blockDim.x + threadIdx.x;
    if (i < rows * K) {
        int row = i / K, k = i - row * K;
        dst[a_shuf_idx_h(row, k, K >> 6)] = __float2half(src[i]);
    }
}
__global__ void shufB2_k(__half* __restrict__ d0, const float* __restrict__ s0,
                         __half* __restrict__ d1, const float* __restrict__ s1,
                         int rows, int rowsPad, int Kin, int Kpad) {
    int i = blockIdx.x * blockDim.x + threadIdx.x;
    if (i < rowsPad * Kpad) {
        int row = i / Kpad, k = i - row * Kpad;
        int idx = b_shuf_idx_h(row, k, Kpad >> 6);
        bool ok = (row < rows) && (k < Kin);
        d0[idx] = __float2half(ok ? s0[row * Kin + k] : 0.f);
        d1[idx] = __float2half(ok ? s1[row * Kin + k] : 0.f);
    }
}
#define N_XPW  (128 * D_INNER)
#define N_OUTW (D_MODEL * D_INNER)
#define N_DTW  (D_INNER * 64)
__global__ void shufW3_k(
    __half* __restrict__ xd0, const float* __restrict__ xs0,
    __half* __restrict__ xd1, const float* __restrict__ xs1,
    __half* __restrict__ od0, const float* __restrict__ os0,
    __half* __restrict__ od1, const float* __restrict__ os1,
    __half* __restrict__ dd0, const float* __restrict__ ds0,
    __half* __restrict__ dd1, const float* __restrict__ ds1)
{
    int i = blockIdx.x * blockDim.x + threadIdx.x;
    if (i < N_XPW) {
        int row = i / D_INNER, k = i - row * D_INNER;
        int idx = b_shuf_idx_h(row, k, D_INNER >> 6);
        bool ok = row < XPROJ;
        xd0[idx] = __float2half(ok ? xs0[row * D_INNER + k] : 0.f);
        xd1[idx] = __float2half(ok ? xs1[row * D_INNER + k] : 0.f);
    } else if (i < N_XPW + N_OUTW) {
        int j = i - N_XPW;
        int row = j / D_INNER, k = j - row * D_INNER;
        int idx = b_shuf_idx_h(row, k, D_INNER >> 6);
        od0[idx] = __float2half(os0[row * D_INNER + k]);
        od1[idx] = __float2half(os1[row * D_INNER + k]);
    } else if (i < N_XPW + N_OUTW + N_DTW) {
        int j = i - N_XPW - N_OUTW;
        int row = j >> 6, k = j & 63;
        int idx = b_shuf_idx_h(row, k, 1);
        bool ok = k < DT_RANK;
        dd0[idx] = __float2half(ok ? ds0[row * DT_RANK + k] : 0.f);
        dd1[idx] = __float2half(ok ? ds1[row * DT_RANK + k] : 0.f);
    }
}

// x_proj split-K reduce: xdbl exact + dtr (A-shuffled fp16, K pad 64)
__global__ void xp_reduce_kernel() {
    int i = blockIdx.x * blockDim.x + threadIdx.x;   // 2*NTOK*64
    if (i >= 2 * NTOK * 64) return;
    int c   = i & 63;
    int tk  = (i >> 6) % NTOK;
    int dir = i / (64 * NTOK);
    float s = 0.f;
    {
        s = g_xppart[dir * 4 + 0][tk][c] + g_xppart[dir * 4 + 1][tk][c]
          + g_xppart[dir * 4 + 2][tk][c] + g_xppart[dir * 4 + 3][tk][c];
        if (c < XPROJ) g_xdbl[dir][tk][c] = s;   // c<64 <= XPROJ=80: cols 64..79 handled below
    }
    // cols 64..79 of xdbl are written by the second pass index range
    g_dtr[dir][a_shuf_idx_h(tk, c, 1)] = __float2half((c < DT_RANK) ? s : 0.f);
}
// second small kernel writes remaining xdbl cols 64..79
__global__ void xp_reduce_tail() {
    int i = blockIdx.x * blockDim.x + threadIdx.x;   // 2*NTOK*16
    if (i >= 2 * NTOK * 16) return;
    int c   = 64 + (i & 15);
    int tk  = (i >> 4) % NTOK;
    int dir = i / (16 * NTOK);
    g_xdbl[dir][tk][c] = g_xppart[dir * 4 + 0][tk][c] + g_xppart[dir * 4 + 1][tk][c]
                       + g_xppart[dir * 4 + 2][tk][c] + g_xppart[dir * 4 + 3][tk][c];
}

__global__ void out_add_kernel(float* __restrict__ out) {
    int i = blockIdx.x * blockDim.x + threadIdx.x;
    if (i < NTOK * D_MODEL / 4) {
        float4 a = ((const float4*)&g_opart[0][0][0])[i];
        float4 b = ((const float4*)&g_opart[1][0][0])[i];
        float4 c = ((const float4*)&g_opart[2][0][0])[i];
        float4 d = ((const float4*)&g_opart[3][0][0])[i];
        a.x += b.x + c.x + d.x;
        a.y += b.y + c.y + d.y;
        a.z += b.z + c.z + d.z;
        a.w += b.w + c.w + d.w;
        ((float4*)out)[i] = a;
    }
}

// ---------------------------------------------------------------------------
// Depthwise causal conv + bias + SiLU: 8 timesteps/thread, rolling window.
// ---------------------------------------------------------------------------
__global__ void __launch_bounds__(256) conv_silu_kernel(
    const float* __restrict__ w_f, const float* __restrict__ b_f,
    const float* __restrict__ w_r, const float* __restrict__ b_r)
{
    int d  = blockIdx.x * 256 + threadIdx.x;
    int t0 = blockIdx.y * 8;
    int zb = blockIdx.z;
    int dir = zb >> 1, b = zb & 1;

    const float* wsrc = dir ? w_r : w_f;
    float w0 = wsrc[d * D_CONV + 0], w1 = wsrc[d * D_CONV + 1];
    float w2 = wsrc[d * D_CONV + 2], w3 = wsrc[d * D_CONV + 3];
    float bias = (dir ? b_r : b_f)[d];

    int base = dir ? t0 : t0 - 3;
    float xv[11];
#pragma unroll
    for (int j = 0; j < 11; j++) {
        int tt = base + j;
        xv[j] = (tt >= 0 && tt < SEQ) ? g_xz[dir][b * SEQ + tt][d] : 0.f;
    }
#pragma unroll
    for (int i = 0; i < 8; i++) {
        float acc;
        if (dir == 0)
            acc = bias + w0 * xv[i] + w1 * xv[i + 1] + w2 * xv[i + 2] + w3 * xv[i + 3];
        else
            acc = bias + w0 * xv[i + 3] + w1 * xv[i + 2] + w2 * xv[i + 1] + w3 * xv[i];
        float v = siluf(acc);
        int tok = b * SEQ + t0 + i;
        g_xc[dir][tok][d] = v;
        g_xcr[dir][a_shuf_idx_h(tok, d, D_INNER / 64)] = __float2half(v);
    }
}

// ---------------------------------------------------------------------------
// Chunked selective scan (2 kernels; chunk-state chain folded into pass2).
// ---------------------------------------------------------------------------
__global__ void __launch_bounds__(128) scan_pass1(
    const float* __restrict__ Alog_f, const float* __restrict__ Alog_r)
{
    int dir = blockIdx.z / SCCH;
    int ci  = blockIdx.z % SCCH;
    int b   = blockIdx.y;
    int d   = blockIdx.x * 128 + threadIdx.x;

    float Av[D_STATE];
    bool fast = load_Av(dir ? Alog_r : Alog_f, d, Av);

    __shared__ float sB[SCLEN][D_STATE];
    for (int j = threadIdx.x; j < SCLEN * D_STATE; j += 128) {
        int lt = j >> 4, n = j & 15;
        int gs = ci * SCLEN + lt;
        int t  = dir ? (SEQ - 1 - gs) : gs;
        sB[lt][n] = g_xdbl[dir][b * SEQ + t][DT_RANK + n];
    }
    __syncthreads();

    float h[D_STATE];
#pragma unroll
    for (int n = 0; n < D_STATE; n++) h[n] = 0.f;
    float sdt = 0.f;

    for (int s = 0; s < SCLEN; s++) {
        int gs  = ci * SCLEN + s;
        int t   = dir ? (SEQ - 1 - gs) : gs;
        int tok = b * SEQ + t;
        float dt  = g_dt[dir][tok][d];
        float x   = g_xc[dir][tok][d];
        float dtx = dt * x;
        sdt += dt;
        if (fast) {
            float r = __expf(dt * Av[0]);
            float dA = r;
#pragma unroll
            for (int n = 0; n < D_STATE; n++) {
                h[n] = fmaf(dA, h[n], dtx * sB[s][n]);
                dA *= r;
            }
        } else {
#pragma unroll
            for (int n = 0; n < D_STATE; n++)
                h[n] = fmaf(__expf(dt * Av[n]), h[n], dtx * sB[s][n]);
        }
    }

    g_sdt[dir][b][ci][d] = sdt;
#pragma unroll
    for (int n = 0; n < D_STATE; n++) g_S[dir][b][ci][n][d] = h[n];
}

__global__ void __launch_bounds__(128) scan_pass2(
    const float* __restrict__ Alog_f, const float* __restrict__ D_f,
    const float* __restrict__ Alog_r, const float* __restrict__ D_r)
{
    int dir = blockIdx.z / SCCH;
    int ci  = blockIdx.z % SCCH;
    int b   = blockIdx.y;
    int d   = blockIdx.x * 128 + threadIdx.x;

    float Av[D_STATE];
    bool fast = load_Av(dir ? Alog_r : Alog_f, d, Av);
    float Dv = (dir ? D_r : D_f)[d];

    __shared__ float sB[SCLEN][D_STATE];
    __shared__ float sC[SCLEN][D_STATE];
    for (int j = threadIdx.x; j < SCLEN * 2 * D_STATE; j += 128) {
        int lt = j >> 5, cc = j & 31;
        int gs = ci * SCLEN + lt;
        int t  = dir ? (SEQ - 1 - gs) : gs;
        float v = g_xdbl[dir][b * SEQ + t][DT_RANK + cc];
        if (cc < D_STATE) sB[lt][cc] = v;
        else              sC[lt][cc - D_STATE] = v;
    }
    __syncthreads();

    // chain chunk states 0..ci-1 (fused scan_prop)
    float h[D_STATE];
#pragma unroll
    for (int n = 0; n < D_STATE; n++) h[n] = 0.f;
    for (int c = 0; c < ci; c++) {
        float sdt = g_sdt[dir][b][c][d];
        if (fast) {
            float r = __expf(sdt * Av[0]);
            float P = r;
#pragma unroll
            for (int n = 0; n < D_STATE; n++) {
                h[n] = fmaf(P, h[n], g_S[dir][b][c][n][d]);
                P *= r;
            }
        } else {
#pragma unroll
            for (int n = 0; n < D_STATE; n++)
                h[n] = fmaf(__expf(sdt * Av[n]), h[n], g_S[dir][b][c][n][d]);
        }
    }

    for (int s = 0; s < SCLEN; s++) {
        int gs  = ci * SCLEN + s;
        int t   = dir ? (SEQ - 1 - gs) : gs;
        int tok = b * SEQ + t;
        float dt  = g_dt[dir][tok][d];
        float x   = g_xc[dir][tok][d];
        float dtx = dt * x;
        float y = 0.f;
        if (fast) {
            float r = __expf(dt * Av[0]);
            float dA = r;
#pragma unroll
            for (int n = 0; n < D_STATE; n++) {
                h[n] = fmaf(dA, h[n], dtx * sB[s][n]);
                y    = fmaf(h[n], sC[s][n], y);
                dA *= r;
            }
        } else {
#pragma unroll
            for (int n = 0; n < D_STATE; n++) {
                h[n] = fmaf(__expf(dt * Av[n]), h[n], dtx * sB[s][n]);
                y    = fmaf(h[n], sC[s][n], y);
            }
        }
        float z = g_xz[dir][tok][D_INNER + d];
        g_y[dir][a_shuf_idx_h(tok, d, D_INNER / 64)] =
            __float2half((y + x * Dv) * siluf(z));
    }
}

// ---------------------------------------------------------------------------
extern "C" void kernel_launch(void* const* d_in, const int* in_sizes, int n_in,
                              void* d_out, int out_size)
{
    (void)in_sizes; (void)n_in; (void)out_size;

    const float* hidden   = (const float*)d_in[0];
    const float* inW[2]   = {(const float*)d_in[1],  (const float*)d_in[10]};
    const float* convW[2] = {(const float*)d_in[2],  (const float*)d_in[11]};
    const float* convB[2] = {(const float*)d_in[3],  (const float*)d_in[12]};
    const float* xpW[2]   = {(const float*)d_in[4],  (const float*)d_in[13]};
    const float* dtW[2]   = {(const float*)d_in[5],  (const float*)d_in[14]};
    const float* dtB[2]   = {(const float*)d_in[6],  (const float*)d_in[15]};
    const float* Alog[2]  = {(const float*)d_in[7],  (const float*)d_in[16]};
    const float* Dp[2]    = {(const float*)d_in[8],  (const float*)d_in[17]};
    const float* outW[2]  = {(const float*)d_in[9],  (const float*)d_in[18]};
    float* out = (float*)d_out;

    float *xz, *dt, *xpp, *opart;
    __half *xcr, *dtr, *y, *hidr, *inWr, *xpWr, *dtWr, *outWr;
    cudaGetSymbolAddress((void**)&xz,    g_xz);
    cudaGetSymbolAddress((void**)&xcr,   g_xcr);
    cudaGetSymbolAddress((void**)&dtr,   g_dtr);
    cudaGetSymbolAddress((void**)&dt,    g_dt);
    cudaGetSymbolAddress((void**)&y,     g_y);
    cudaGetSymbolAddress((void**)&hidr,  g_hidr);
    cudaGetSymbolAddress((void**)&inWr,  g_inWr);
    cudaGetSymbolAddress((void**)&xpWr,  g_xpWr);
    cudaGetSymbolAddress((void**)&dtWr,  g_dtWr);
    cudaGetSymbolAddress((void**)&outWr, g_outWr);
    cudaGetSymbolAddress((void**)&xpp,   g_xppart);
    cudaGetSymbolAddress((void**)&opart, g_opart);

    cudaFuncSetAttribute(gemm_tc, cudaFuncAttributeMaxDynamicSharedMemorySize, DYN_SMEM);

    const long long szXC   = (long long)NTOK * D_INNER;   // halves (xcr, y)
    const long long szXZ   = (long long)NTOK * 2 * D_INNER;
    const long long szINW  = (long long)2 * D_INNER * D_MODEL;
    const long long szXPW  = (long long)128 * D_INNER;
    const long long szDTW  = (long long)D_INNER * 64 + PANEL_H;
    const long long szOUTW = (long long)D_MODEL * D_INNER;
    const long long szDTR  = (long long)NTOK * 64 + PANEL_H;
    const long long szXPP  = (long long)NTOK * XPROJ;
    const long long szOP   = (long long)NTOK * D_MODEL;

    // 0) shuffle+round pre-passes — 3 launches
    {
        int n = NTOK * D_MODEL;
        shufA_k<<<(n + 255) / 256, 256>>>(hidr, hidden, NTOK, D_MODEL);
        n = 2 * D_INNER * D_MODEL;
        shufB2_k<<<(n + 255) / 256, 256>>>(inWr, inW[0], inWr + szINW, inW[1],
                                           2 * D_INNER, 2 * D_INNER, D_MODEL, D_MODEL);
        n = N_XPW + N_OUTW + N_DTW;
        shufW3_k<<<(n + 255) / 256, 256>>>(
            xpWr, xpW[0], xpWr + szXPW, xpW[1],
            outWr, outW[0], outWr + szOUTW, outW[1],
            dtWr, dtW[0], dtWr + szDTW, dtW[1]);
    }

    // 1) in_proj (launch #4 — ncu target): panels=12, nch=12
    gemm_tc<<<dim3((2 * D_INNER) / 128, NTOK / 128, 2), 128, DYN_SMEM>>>(
        hidr, hidr, inWr, inWr + szINW,
        D_MODEL / 64, D_MODEL / 64, 1,
        xz, szXZ, 2 * D_INNER, 2 * D_INNER, nullptr, nullptr, 0);

    // 2) conv + silu
    conv_silu_kernel<<<dim3(D_INNER / 256, SEQ / 8, 4), 256>>>(
        convW[0], convB[0], convW[1], convB[1]);

    // 3) x_proj split-K x4 + reduce: panels=24, nchLoc=6
    gemm_tc<<<dim3(1, NTOK / 128, 8), 128, DYN_SMEM>>>(
        xcr, xcr + szXC, xpWr, xpWr + szXPW,
        D_INNER / 64, D_INNER / 256, 4,
        xpp, szXPP, XPROJ, XPROJ, nullptr, nullptr, 0);
    xp_reduce_kernel<<<(2 * NTOK * 64 + 255) / 256, 256>>>();
    xp_reduce_tail<<<(2 * NTOK * 16 + 255) / 256, 256>>>();

    // 4) dt_proj (K pad 64, nch=1): panels=1
    gemm_tc<<<dim3(D_INNER / 128, NTOK / 128, 2), 128, DYN_SMEM>>>(
        dtr, dtr + szDTR, dtWr, dtWr + szDTW,
        1, 1, 1,
        dt, szXC, D_INNER, D_INNER, dtB[0], dtB[1], 2);

    // 5) chunked selective scan (prop folded into pass2)
    scan_pass1<<<dim3(D_INNER / 128, BATCH, 2 * SCCH), 128>>>(Alog[0], Alog[1]);
    scan_pass2<<<dim3(D_INNER / 128, BATCH, 2 * SCCH), 128>>>(
        Alog[0], Dp[0], Alog[1], Dp[1]);

    // 6) out_proj split-K x2 per dir (z = dir*2 + split), K=768 each + add
    gemm_tc<<<dim3(D_MODEL / 128, NTOK / 128, 4), 128, DYN_SMEM>>>(
        y, y + szXC, outWr, outWr + szOUTW,
        D_INNER / 64, D_INNER / 128, 2,
        opart, szOP, D_MODEL, D_MODEL, nullptr, nullptr, 0);
    out_add_kernel<<<(NTOK * D_MODEL / 4 + 255) / 256, 256>>>(out);
}

// round 17
// speedup vs baseline: 1.3824x; 1.0283x over previous
#include <cuda_runtime.h>
#include <cuda_fp16.h>
#include <math.h>
#include <stdint.h>

#define D_MODEL 768
#define D_INNER 1536
#define D_STATE 16
#define D_CONV  4
#define DT_RANK 48
#define BATCH   2
#define SEQ     2048
#define NTOK    (BATCH*SEQ)
#define XPROJ   80
#define SCCH    16
#define SCLEN   (SEQ/SCCH)

#define BK      64
#define NST     3
#define PANEL_H 8192                   // halves per 128x64 panel (16KB)
#define STAGE_B 16384                  // bytes per stage per matrix
#define DYN_SMEM (NST * STAGE_B * 2)   // 96KB -> 2 CTAs/SM

// ---------------- scratch (static device globals; no allocs) ----------------
static __device__ float  g_xz   [2][NTOK][2*D_INNER];
static __device__ float  g_xc   [2][NTOK][D_INNER];
static __device__ __half g_xcr  [2][NTOK*D_INNER];      // A-shuffled fp16
static __device__ float  g_xdbl [2][NTOK][XPROJ];
static __device__ float  g_xppart[8][NTOK][XPROJ];
static __device__ __half g_dtr  [2][NTOK*64 + PANEL_H]; // A-shuffled, K pad 64 (+prologue slack)
static __device__ float  g_dt   [2][NTOK][D_INNER];
static __device__ __half g_y    [2][NTOK*D_INNER];      // A-shuffled fp16
static __device__ float  g_opart[4][NTOK][D_MODEL];     // out_proj: 2 dirs x 2 K-splits
static __device__ __half g_hidr [NTOK*D_MODEL];
static __device__ __half g_inWr [2][2*D_INNER*D_MODEL];
static __device__ __half g_xpWr [2][128*D_INNER];
static __device__ __half g_dtWr [2][D_INNER*64 + PANEL_H];
static __device__ __half g_outWr[2][D_MODEL*D_INNER];
// chunked-scan state
static __device__ float g_S  [2][BATCH][SCCH][D_STATE][D_INNER];
static __device__ float g_sdt[2][BATCH][SCCH][D_INNER];

__device__ __forceinline__ float siluf(float v)     { return v / (1.f + __expf(-v)); }
__device__ __forceinline__ float softplusf(float v) { return fmaxf(v, 0.f) + log1pf(__expf(-fabsf(v))); }

// fragment-packed fp16 layouts for mma.m16n8k16 (indices in half units)
__device__ __forceinline__ int a_shuf_idx_h(int row, int k, int panelsTot) {
    int grp = row >> 7, r7 = row & 127, mt = r7 >> 4, r = r7 & 15;
    int p = k >> 6, k6 = k & 63, kt = k6 >> 4, kk = k6 & 15;
    int lane = (r & 7) * 4 + ((kk >> 1) & 3);
    int reg  = ((r >> 3) & 1) + ((kk >> 3) << 1);
    return (grp * panelsTot + p) * PANEL_H + (mt * 4 + kt) * 256 + lane * 8 + reg * 2 + (kk & 1);
}
__device__ __forceinline__ int b_shuf_idx_h(int n, int k, int panelsTot) {
    int grp = n >> 7, n7 = n & 127, nt = n7 >> 3, nn = n7 & 7;
    int p = k >> 6, k6 = k & 63, kt = k6 >> 4, kk = k6 & 15;
    int lane = nn * 4 + ((kk >> 1) & 3);
    int reg  = kk >> 3;
    return (grp * panelsTot + p) * PANEL_H + (nt * 4 + kt) * 128 + lane * 4 + reg * 2 + (kk & 1);
}
__device__ __forceinline__ uint32_t smem_u32(const void* p) {
    uint32_t a;
    asm("{ .reg .u64 t; cvta.to.shared.u64 t, %1; cvt.u32.u64 %0, t; }" : "=r"(a) : "l"(p));
    return a;
}
__device__ __forceinline__ void cpasync16(uint32_t dst, const void* src) {
    asm volatile("cp.async.cg.shared.global [%0], [%1], 16;"
                 :: "r"(dst), "l"(src) : "memory");
}
#define CP_COMMIT() asm volatile("cp.async.commit_group;" ::: "memory")
#define CP_WAIT1()  asm volatile("cp.async.wait_group 1;" ::: "memory")

__device__ __forceinline__ void mma16h(float* d, const uint32_t* a, const uint32_t* b) {
    asm volatile(
        "mma.sync.aligned.m16n8k16.row.col.f32.f16.f16.f32 "
        "{%0,%1,%2,%3}, {%4,%5,%6,%7}, {%8,%9}, {%0,%1,%2,%3};"
        : "+f"(d[0]), "+f"(d[1]), "+f"(d[2]), "+f"(d[3])
        : "r"(a[0]), "r"(a[1]), "r"(a[2]), "r"(a[3]), "r"(b[0]), "r"(b[1]));
}

// load Av and check geometric structure A_n = n*A_1
__device__ __forceinline__ bool load_Av(const float* Alog, int d, float* Av) {
    bool fast = true;
#pragma unroll
    for (int n = 0; n < D_STATE; n++) {
        Av[n] = -__expf(Alog[d * D_STATE + n]);
        fast = fast && (fabsf(Av[n] - (n + 1) * Av[0]) <= 1e-3f * fabsf(Av[n]) + 1e-9f);
    }
    return fast;
}

// ---------------------------------------------------------------------------
// fp16 GEMM (m16n8k16), fragment-shuffled operands. 128x128 CTA tile, BK=64,
// 256 threads / 8 warps (2x4), 64x32 warp tile -> 16 warps/SM at 2 CTAs/SM.
// z: dir = z/zDiv, split = z%zDiv. mode 0: store; 2: softplus(v + bias[n]).
// NOTE: prologue issues 2 chunks; callers with nchLoc==1 need 1 panel slack.
// ---------------------------------------------------------------------------
__global__ void __launch_bounds__(256, 2) gemm_tc(
    const __half* A0, const __half* A1,
    const __half* B0, const __half* B1,
    int panelsTot, int nchLoc, int zDiv,
    float* C, long long cZStride, int ldc, int Nfull,
    const float* bias0, const float* bias1, int mode)
{
    extern __shared__ __half hsm[];
    const uint32_t aA = smem_u32(hsm);
    const uint32_t aB = aA + NST * STAGE_B;

    const int tid    = threadIdx.x;
    const int lane   = tid & 31;
    const int wid    = tid >> 5;
    const int warp_m = wid & 1;          // 0..1 -> 64 rows
    const int warp_n = wid >> 1;         // 0..3 -> 32 cols
    const int g      = lane >> 2;
    const int t      = lane & 3;
    const int z      = blockIdx.z;
    const int dir    = z / zDiv;
    const int split  = z - dir * zDiv;
    const int bm     = blockIdx.y * 128;
    const int bn     = blockIdx.x * 128;

    const __half* A = (dir ? A1 : A0)
        + (size_t)((bm >> 7) * panelsTot + split * nchLoc) * PANEL_H;
    const __half* B = (dir ? B1 : B0)
        + (size_t)((bn >> 7) * panelsTot + split * nchLoc) * PANEL_H;
    const float* bias = dir ? bias1 : bias0;
    float* Cz = C + (long long)z * cZStride;

    // producer: 4x16B per matrix per thread per chunk (pure linear copy)
    const __half* pA = A + tid * 8;
    const __half* pB = B + tid * 8;
    const uint32_t soff = (uint32_t)tid * 16;
    uint32_t stWr = 0;
    auto issue = [&]() {
#pragma unroll
        for (int i = 0; i < 4; i++) {
            cpasync16(aA + stWr + soff + i * 4096, pA + i * 2048);
            cpasync16(aB + stWr + soff + i * 4096, pB + i * 2048);
        }
        CP_COMMIT();
        pA += PANEL_H; pB += PANEL_H;
        stWr += STAGE_B;
        if (stWr == NST * STAGE_B) stWr = 0;
    };

    float acc[4][4][4];
#pragma unroll
    for (int mi = 0; mi < 4; mi++)
#pragma unroll
        for (int ni = 0; ni < 4; ni++)
#pragma unroll
            for (int r = 0; r < 4; r++) acc[mi][ni][r] = 0.f;

    issue();
    issue();

    uint32_t stRd = 0;
    for (int c = 0; c < nchLoc; c++) {
        CP_WAIT1();
        __syncthreads();
        if (c + NST - 1 < nchLoc) issue();
        else                      CP_COMMIT();

        const __half* A_ = hsm + (stRd >> 1);
        const __half* B_ = A_ + NST * PANEL_H;
        stRd += STAGE_B;
        if (stRd == NST * STAGE_B) stRd = 0;

#pragma unroll
        for (int ks = 0; ks < 4; ks++) {
            uint4 af[4];
            uint2 bf[4];
#pragma unroll
            for (int mi = 0; mi < 4; mi++)
                af[mi] = *(const uint4*)(A_ + ((warp_m * 4 + mi) * 4 + ks) * 256 + lane * 8);
#pragma unroll
            for (int ni = 0; ni < 4; ni++)
                bf[ni] = *(const uint2*)(B_ + ((warp_n * 4 + ni) * 4 + ks) * 128 + lane * 4);
#pragma unroll
            for (int mi = 0; mi < 4; mi++) {
                uint32_t au[4] = { af[mi].x, af[mi].y, af[mi].z, af[mi].w };
#pragma unroll
                for (int ni = 0; ni < 4; ni++) {
                    uint32_t bu[2] = { bf[ni].x, bf[ni].y };
                    mma16h(acc[mi][ni], au, bu);
                }
            }
        }
    }

#pragma unroll
    for (int mi = 0; mi < 4; mi++) {
        int row = bm + warp_m * 64 + mi * 16 + g;
#pragma unroll
        for (int ni = 0; ni < 4; ni++) {
            int col = bn + warp_n * 32 + ni * 8 + t * 2;
            if (col < Nfull) {
                float v00 = acc[mi][ni][0], v01 = acc[mi][ni][1];
                float v10 = acc[mi][ni][2], v11 = acc[mi][ni][3];
                if (mode == 2) {
                    float b0 = bias[col], b1 = bias[col + 1];
                    v00 = softplusf(v00 + b0); v01 = softplusf(v01 + b1);
                    v10 = softplusf(v10 + b0); v11 = softplusf(v11 + b1);
                }
                *(float2*)(Cz + (size_t)row * ldc + col)       = make_float2(v00, v01);
                *(float2*)(Cz + (size_t)(row + 8) * ldc + col) = make_float2(v10, v11);
            }
        }
    }
}

// ---------------------------------------------------------------------------
// Shuffle pre-passes (3 launches; in_proj gemm is launch #4 for ncu)
// ---------------------------------------------------------------------------
__global__ void shufA_k(__half* __restrict__ dst, const float* __restrict__ src,
                        int rows, int K) {
    int i = blockIdx.x * blockDim.x + threadIdx.x;
    if (i < rows * K) {
        int row = i / K, k = i - row * K;
        dst[a_shuf_idx_h(row, k, K >> 6)] = __float2half(src[i]);
    }
}
__global__ void shufB2_k(__half* __restrict__ d0, const float* __restrict__ s0,
                         __half* __restrict__ d1, const float* __restrict__ s1,
                         int rows, int rowsPad, int Kin, int Kpad) {
    int i = blockIdx.x * blockDim.x + threadIdx.x;
    if (i < rowsPad * Kpad) {
        int row = i / Kpad, k = i - row * Kpad;
        int idx = b_shuf_idx_h(row, k, Kpad >> 6);
        bool ok = (row < rows) && (k < Kin);
        d0[idx] = __float2half(ok ? s0[row * Kin + k] : 0.f);
        d1[idx] = __float2half(ok ? s1[row * Kin + k] : 0.f);
    }
}
#define N_XPW  (128 * D_INNER)
#define N_OUTW (D_MODEL * D_INNER)
#define N_DTW  (D_INNER * 64)
__global__ void shufW3_k(
    __half* __restrict__ xd0, const float* __restrict__ xs0,
    __half* __restrict__ xd1, const float* __restrict__ xs1,
    __half* __restrict__ od0, const float* __restrict__ os0,
    __half* __restrict__ od1, const float* __restrict__ os1,
    __half* __restrict__ dd0, const float* __restrict__ ds0,
    __half* __restrict__ dd1, const float* __restrict__ ds1)
{
    int i = blockIdx.x * blockDim.x + threadIdx.x;
    if (i < N_XPW) {
        int row = i / D_INNER, k = i - row * D_INNER;
        int idx = b_shuf_idx_h(row, k, D_INNER >> 6);
        bool ok = row < XPROJ;
        xd0[idx] = __float2half(ok ? xs0[row * D_INNER + k] : 0.f);
        xd1[idx] = __float2half(ok ? xs1[row * D_INNER + k] : 0.f);
    } else if (i < N_XPW + N_OUTW) {
        int j = i - N_XPW;
        int row = j / D_INNER, k = j - row * D_INNER;
        int idx = b_shuf_idx_h(row, k, D_INNER >> 6);
        od0[idx] = __float2half(os0[row * D_INNER + k]);
        od1[idx] = __float2half(os1[row * D_INNER + k]);
    } else if (i < N_XPW + N_OUTW + N_DTW) {
        int j = i - N_XPW - N_OUTW;
        int row = j >> 6, k = j & 63;
        int idx = b_shuf_idx_h(row, k, 1);
        bool ok = k < DT_RANK;
        dd0[idx] = __float2half(ok ? ds0[row * DT_RANK + k] : 0.f);
        dd1[idx] = __float2half(ok ? ds1[row * DT_RANK + k] : 0.f);
    }
}

// x_proj split-K reduce: xdbl exact + dtr (A-shuffled fp16, K pad 64)
__global__ void xp_reduce_kernel() {
    int i = blockIdx.x * blockDim.x + threadIdx.x;   // 2*NTOK*64
    if (i >= 2 * NTOK * 64) return;
    int c   = i & 63;
    int tk  = (i >> 6) % NTOK;
    int dir = i / (64 * NTOK);
    float s = g_xppart[dir * 4 + 0][tk][c] + g_xppart[dir * 4 + 1][tk][c]
            + g_xppart[dir * 4 + 2][tk][c] + g_xppart[dir * 4 + 3][tk][c];
    g_xdbl[dir][tk][c] = s;
    g_dtr[dir][a_shuf_idx_h(tk, c, 1)] = __float2half((c < DT_RANK) ? s : 0.f);
}
__global__ void xp_reduce_tail() {
    int i = blockIdx.x * blockDim.x + threadIdx.x;   // 2*NTOK*16
    if (i >= 2 * NTOK * 16) return;
    int c   = 64 + (i & 15);
    int tk  = (i >> 4) % NTOK;
    int dir = i / (16 * NTOK);
    g_xdbl[dir][tk][c] = g_xppart[dir * 4 + 0][tk][c] + g_xppart[dir * 4 + 1][tk][c]
                       + g_xppart[dir * 4 + 2][tk][c] + g_xppart[dir * 4 + 3][tk][c];
}

__global__ void out_add_kernel(float* __restrict__ out) {
    int i = blockIdx.x * blockDim.x + threadIdx.x;
    if (i < NTOK * D_MODEL / 4) {
        float4 a = ((const float4*)&g_opart[0][0][0])[i];
        float4 b = ((const float4*)&g_opart[1][0][0])[i];
        float4 c = ((const float4*)&g_opart[2][0][0])[i];
        float4 d = ((const float4*)&g_opart[3][0][0])[i];
        a.x += b.x + c.x + d.x;
        a.y += b.y + c.y + d.y;
        a.z += b.z + c.z + d.z;
        a.w += b.w + c.w + d.w;
        ((float4*)out)[i] = a;
    }
}

// ---------------------------------------------------------------------------
// Depthwise causal conv + bias + SiLU: 8 timesteps/thread, rolling window.
// ---------------------------------------------------------------------------
__global__ void __launch_bounds__(256) conv_silu_kernel(
    const float* __restrict__ w_f, const float* __restrict__ b_f,
    const float* __restrict__ w_r, const float* __restrict__ b_r)
{
    int d  = blockIdx.x * 256 + threadIdx.x;
    int t0 = blockIdx.y * 8;
    int zb = blockIdx.z;
    int dir = zb >> 1, b = zb & 1;

    const float* wsrc = dir ? w_r : w_f;
    float w0 = wsrc[d * D_CONV + 0], w1 = wsrc[d * D_CONV + 1];
    float w2 = wsrc[d * D_CONV + 2], w3 = wsrc[d * D_CONV + 3];
    float bias = (dir ? b_r : b_f)[d];

    int base = dir ? t0 : t0 - 3;
    float xv[11];
#pragma unroll
    for (int j = 0; j < 11; j++) {
        int tt = base + j;
        xv[j] = (tt >= 0 && tt < SEQ) ? g_xz[dir][b * SEQ + tt][d] : 0.f;
    }
#pragma unroll
    for (int i = 0; i < 8; i++) {
        float acc;
        if (dir == 0)
            acc = bias + w0 * xv[i] + w1 * xv[i + 1] + w2 * xv[i + 2] + w3 * xv[i + 3];
        else
            acc = bias + w0 * xv[i + 3] + w1 * xv[i + 2] + w2 * xv[i + 1] + w3 * xv[i];
        float v = siluf(acc);
        int tok = b * SEQ + t0 + i;
        g_xc[dir][tok][d] = v;
        g_xcr[dir][a_shuf_idx_h(tok, d, D_INNER / 64)] = __float2half(v);
    }
}

// ---------------------------------------------------------------------------
// Chunked selective scan (2 kernels; chunk-state chain folded into pass2).
// ---------------------------------------------------------------------------
__global__ void __launch_bounds__(128) scan_pass1(
    const float* __restrict__ Alog_f, const float* __restrict__ Alog_r)
{
    int dir = blockIdx.z / SCCH;
    int ci  = blockIdx.z % SCCH;
    int b   = blockIdx.y;
    int d   = blockIdx.x * 128 + threadIdx.x;

    float Av[D_STATE];
    bool fast = load_Av(dir ? Alog_r : Alog_f, d, Av);

    __shared__ float sB[SCLEN][D_STATE];
    for (int j = threadIdx.x; j < SCLEN * D_STATE; j += 128) {
        int lt = j >> 4, n = j & 15;
        int gs = ci * SCLEN + lt;
        int t  = dir ? (SEQ - 1 - gs) : gs;
        sB[lt][n] = g_xdbl[dir][b * SEQ + t][DT_RANK + n];
    }
    __syncthreads();

    float h[D_STATE];
#pragma unroll
    for (int n = 0; n < D_STATE; n++) h[n] = 0.f;
    float sdt = 0.f;

    for (int s = 0; s < SCLEN; s++) {
        int gs  = ci * SCLEN + s;
        int t   = dir ? (SEQ - 1 - gs) : gs;
        int tok = b * SEQ + t;
        float dt  = g_dt[dir][tok][d];
        float x   = g_xc[dir][tok][d];
        float dtx = dt * x;
        sdt += dt;
        if (fast) {
            float r = __expf(dt * Av[0]);
            float dA = r;
#pragma unroll
            for (int n = 0; n < D_STATE; n++) {
                h[n] = fmaf(dA, h[n], dtx * sB[s][n]);
                dA *= r;
            }
        } else {
#pragma unroll
            for (int n = 0; n < D_STATE; n++)
                h[n] = fmaf(__expf(dt * Av[n]), h[n], dtx * sB[s][n]);
        }
    }

    g_sdt[dir][b][ci][d] = sdt;
#pragma unroll
    for (int n = 0; n < D_STATE; n++) g_S[dir][b][ci][n][d] = h[n];
}

__global__ void __launch_bounds__(128) scan_pass2(
    const float* __restrict__ Alog_f, const float* __restrict__ D_f,
    const float* __restrict__ Alog_r, const float* __restrict__ D_r)
{
    int dir = blockIdx.z / SCCH;
    int ci  = blockIdx.z % SCCH;
    int b   = blockIdx.y;
    int d   = blockIdx.x * 128 + threadIdx.x;

    float Av[D_STATE];
    bool fast = load_Av(dir ? Alog_r : Alog_f, d, Av);
    float Dv = (dir ? D_r : D_f)[d];

    __shared__ float sB[SCLEN][D_STATE];
    __shared__ float sC[SCLEN][D_STATE];
    for (int j = threadIdx.x; j < SCLEN * 2 * D_STATE; j += 128) {
        int lt = j >> 5, cc = j & 31;
        int gs = ci * SCLEN + lt;
        int t  = dir ? (SEQ - 1 - gs) : gs;
        float v = g_xdbl[dir][b * SEQ + t][DT_RANK + cc];
        if (cc < D_STATE) sB[lt][cc] = v;
        else              sC[lt][cc - D_STATE] = v;
    }
    __syncthreads();

    // chain chunk states 0..ci-1 (fused scan_prop)
    float h[D_STATE];
#pragma unroll
    for (int n = 0; n < D_STATE; n++) h[n] = 0.f;
    for (int c = 0; c < ci; c++) {
        float sdt = g_sdt[dir][b][c][d];
        if (fast) {
            float r = __expf(sdt * Av[0]);
            float P = r;
#pragma unroll
            for (int n = 0; n < D_STATE; n++) {
                h[n] = fmaf(P, h[n], g_S[dir][b][c][n][d]);
                P *= r;
            }
        } else {
#pragma unroll
            for (int n = 0; n < D_STATE; n++)
                h[n] = fmaf(__expf(sdt * Av[n]), h[n], g_S[dir][b][c][n][d]);
        }
    }

    for (int s = 0; s < SCLEN; s++) {
        int gs  = ci * SCLEN + s;
        int t   = dir ? (SEQ - 1 - gs) : gs;
        int tok = b * SEQ + t;
        float dt  = g_dt[dir][tok][d];
        float x   = g_xc[dir][tok][d];
        float dtx = dt * x;
        float y = 0.f;
        if (fast) {
            float r = __expf(dt * Av[0]);
            float dA = r;
#pragma unroll
            for (int n = 0; n < D_STATE; n++) {
                h[n] = fmaf(dA, h[n], dtx * sB[s][n]);
                y    = fmaf(h[n], sC[s][n], y);
                dA *= r;
            }
        } else {
#pragma unroll
            for (int n = 0; n < D_STATE; n++) {
                h[n] = fmaf(__expf(dt * Av[n]), h[n], dtx * sB[s][n]);
                y    = fmaf(h[n], sC[s][n], y);
            }
        }
        float z = g_xz[dir][tok][D_INNER + d];
        g_y[dir][a_shuf_idx_h(tok, d, D_INNER / 64)] =
            __float2half((y + x * Dv) * siluf(z));
    }
}

// ---------------------------------------------------------------------------
extern "C" void kernel_launch(void* const* d_in, const int* in_sizes, int n_in,
                              void* d_out, int out_size)
{
    (void)in_sizes; (void)n_in; (void)out_size;

    const float* hidden   = (const float*)d_in[0];
    const float* inW[2]   = {(const float*)d_in[1],  (const float*)d_in[10]};
    const float* convW[2] = {(const float*)d_in[2],  (const float*)d_in[11]};
    const float* convB[2] = {(const float*)d_in[3],  (const float*)d_in[12]};
    const float* xpW[2]   = {(const float*)d_in[4],  (const float*)d_in[13]};
    const float* dtW[2]   = {(const float*)d_in[5],  (const float*)d_in[14]};
    const float* dtB[2]   = {(const float*)d_in[6],  (const float*)d_in[15]};
    const float* Alog[2]  = {(const float*)d_in[7],  (const float*)d_in[16]};
    const float* Dp[2]    = {(const float*)d_in[8],  (const float*)d_in[17]};
    const float* outW[2]  = {(const float*)d_in[9],  (const float*)d_in[18]};
    float* out = (float*)d_out;

    float *xz, *dt, *xpp, *opart;
    __half *xcr, *dtr, *y, *hidr, *inWr, *xpWr, *dtWr, *outWr;
    cudaGetSymbolAddress((void**)&xz,    g_xz);
    cudaGetSymbolAddress((void**)&xcr,   g_xcr);
    cudaGetSymbolAddress((void**)&dtr,   g_dtr);
    cudaGetSymbolAddress((void**)&dt,    g_dt);
    cudaGetSymbolAddress((void**)&y,     g_y);
    cudaGetSymbolAddress((void**)&hidr,  g_hidr);
    cudaGetSymbolAddress((void**)&inWr,  g_inWr);
    cudaGetSymbolAddress((void**)&xpWr,  g_xpWr);
    cudaGetSymbolAddress((void**)&dtWr,  g_dtWr);
    cudaGetSymbolAddress((void**)&outWr, g_outWr);
    cudaGetSymbolAddress((void**)&xpp,   g_xppart);
    cudaGetSymbolAddress((void**)&opart, g_opart);

    cudaFuncSetAttribute(gemm_tc, cudaFuncAttributeMaxDynamicSharedMemorySize, DYN_SMEM);

    const long long szXC   = (long long)NTOK * D_INNER;   // halves (xcr, y)
    const long long szXZ   = (long long)NTOK * 2 * D_INNER;
    const long long szINW  = (long long)2 * D_INNER * D_MODEL;
    const long long szXPW  = (long long)128 * D_INNER;
    const long long szDTW  = (long long)D_INNER * 64 + PANEL_H;
    const long long szOUTW = (long long)D_MODEL * D_INNER;
    const long long szDTR  = (long long)NTOK * 64 + PANEL_H;
    const long long szXPP  = (long long)NTOK * XPROJ;
    const long long szOP   = (long long)NTOK * D_MODEL;

    // 0) shuffle+round pre-passes — 3 launches
    {
        int n = NTOK * D_MODEL;
        shufA_k<<<(n + 255) / 256, 256>>>(hidr, hidden, NTOK, D_MODEL);
        n = 2 * D_INNER * D_MODEL;
        shufB2_k<<<(n + 255) / 256, 256>>>(inWr, inW[0], inWr + szINW, inW[1],
                                           2 * D_INNER, 2 * D_INNER, D_MODEL, D_MODEL);
        n = N_XPW + N_OUTW + N_DTW;
        shufW3_k<<<(n + 255) / 256, 256>>>(
            xpWr, xpW[0], xpWr + szXPW, xpW[1],
            outWr, outW[0], outWr + szOUTW, outW[1],
            dtWr, dtW[0], dtWr + szDTW, dtW[1]);
    }

    // 1) in_proj (launch #4 — ncu target): panels=12, nch=12
    gemm_tc<<<dim3((2 * D_INNER) / 128, NTOK / 128, 2), 256, DYN_SMEM>>>(
        hidr, hidr, inWr, inWr + szINW,
        D_MODEL / 64, D_MODEL / 64, 1,
        xz, szXZ, 2 * D_INNER, 2 * D_INNER, nullptr, nullptr, 0);

    // 2) conv + silu
    conv_silu_kernel<<<dim3(D_INNER / 256, SEQ / 8, 4), 256>>>(
        convW[0], convB[0], convW[1], convB[1]);

    // 3) x_proj split-K x4 + reduce: panels=24, nchLoc=6
    gemm_tc<<<dim3(1, NTOK / 128, 8), 256, DYN_SMEM>>>(
        xcr, xcr + szXC, xpWr, xpWr + szXPW,
        D_INNER / 64, D_INNER / 256, 4,
        xpp, szXPP, XPROJ, XPROJ, nullptr, nullptr, 0);
    xp_reduce_kernel<<<(2 * NTOK * 64 + 255) / 256, 256>>>();
    xp_reduce_tail<<<(2 * NTOK * 16 + 255) / 256, 256>>>();

    // 4) dt_proj (K pad 64, nch=1): panels=1
    gemm_tc<<<dim3(D_INNER / 128, NTOK / 128, 2), 256, DYN_SMEM>>>(
        dtr, dtr + szDTR, dtWr, dtWr + szDTW,
        1, 1, 1,
        dt, szXC, D_INNER, D_INNER, dtB[0], dtB[1], 2);

    // 5) chunked selective scan (prop folded into pass2)
    scan_pass1<<<dim3(D_INNER / 128, BATCH, 2 * SCCH), 128>>>(Alog[0], Alog[1]);
    scan_pass2<<<dim3(D_INNER / 128, BATCH, 2 * SCCH), 128>>>(
        Alog[0], Dp[0], Alog[1], Dp[1]);

    // 6) out_proj split-K x2 per dir (z = dir*2 + split), K=768 each + add
    gemm_tc<<<dim3(D_MODEL / 128, NTOK / 128, 4), 256, DYN_SMEM>>>(
        y, y + szXC, outWr, outWr + szOUTW,
        D_INNER / 64, D_INNER / 128, 2,
        opart, szOP, D_MODEL, D_MODEL, nullptr, nullptr, 0);
    out_add_kernel<<<(NTOK * D_MODEL / 4 + 255) / 256, 256>>>(out);
}